// round 12
// baseline (speedup 1.0000x reference)
#include <cuda_runtime.h>
#include <cuda_bf16.h>
#include <math.h>
#include <stdint.h>

#define NN  128000   // B*NPG nodes
#define EE  2048000  // B*EPG edges
#define BBG 128      // graphs
#define NPG 1000
#define EPG 16000
#define DD  128
#define KK  64
#define EPAD 24000   // padded per-graph CSR capacity

// ---------------- scratch (static device globals; no allocs) ----------------
__device__ int      g_deg[NN];
__device__ float    g_dinv[NN];
__device__ int      g_rowptr[NN];              // graph-LOCAL padded CSR offset (mult of 8)
__device__ unsigned short g_csr16[BBG * EPAD]; // graph-local src index per edge
__device__ float    g_bufA[(size_t)NN * DD];
__device__ float    g_bufB[(size_t)NN * DD];
__device__ float    g_pool[BBG * DD];
// bf16 hi/lo weight images, PRE-SWIZZLED into the exact smem byte layout
__device__ char  g_Wh_pre[32768];
__device__ char  g_Wl_pre[32768];
__device__ char  g_Wh_emb[32768];
__device__ char  g_Wl_emb[32768];

// ---------------- packed f32x2 helpers (proven R2) -----------------------------
__device__ __forceinline__ void add2(unsigned long long& d, unsigned long long s) {
    asm("add.rn.f32x2 %0, %0, %1;" : "+l"(d) : "l"(s));
}
__device__ __forceinline__ float2 unpack2(unsigned long long v) {
    unsigned lo, hi;
    asm("mov.b64 {%0, %1}, %2;" : "=r"(lo), "=r"(hi) : "l"(v));
    return make_float2(__uint_as_float(lo), __uint_as_float(hi));
}

// ---------------- warp-MMA helpers (base ISA; proven R9/R10) ------------------
__device__ __forceinline__ uint32_t smem_u32(const void* p) {
    uint32_t a;
    asm("{ .reg .u64 t; cvta.to.shared.u64 t, %1; cvt.u32.u64 %0, t; }" : "=r"(a) : "l"(p));
    return a;
}
__device__ __forceinline__ void ldsm_x4(uint32_t* r, uint32_t a) {
    asm volatile("ldmatrix.sync.aligned.m8n8.x4.shared.b16 {%0,%1,%2,%3}, [%4];"
                 : "=r"(r[0]), "=r"(r[1]), "=r"(r[2]), "=r"(r[3]) : "r"(a));
}
__device__ __forceinline__ void ldsm_x2t(uint32_t* r, uint32_t a) {
    asm volatile("ldmatrix.sync.aligned.m8n8.x2.trans.shared.b16 {%0,%1}, [%2];"
                 : "=r"(r[0]), "=r"(r[1]) : "r"(a));
}
__device__ __forceinline__ void mma16816(float* d, const uint32_t* a, const uint32_t* b) {
    asm volatile("mma.sync.aligned.m16n8k16.row.col.f32.bf16.bf16.f32 "
                 "{%0,%1,%2,%3}, {%4,%5,%6,%7}, {%8,%9}, {%0,%1,%2,%3};"
                 : "+f"(d[0]), "+f"(d[1]), "+f"(d[2]), "+f"(d[3])
                 : "r"(a[0]), "r"(a[1]), "r"(a[2]), "r"(a[3]), "r"(b[0]), "r"(b[1]));
}
__device__ __forceinline__ uint32_t pack_bf16(__nv_bfloat16 lo, __nv_bfloat16 hi) {
    return ((uint32_t)__bfloat16_as_ushort(hi) << 16) | __bfloat16_as_ushort(lo);
}

// ---------------- fused CSR build (padded, u16 indices; proven R11) -----------
__global__ __launch_bounds__(1024) void k_build(const int* __restrict__ src,
                                                const int* __restrict__ dst) {
    __shared__ int cnt[NPG];
    __shared__ int ws[32];
    int b = blockIdx.x;
    int t = threadIdx.x;
    int ebase = b * EPG;
    int nbase = b * NPG;

    if (t < NPG) cnt[t] = 0;
    __syncthreads();

    for (int e = t; e < EPG; e += 1024)
        atomicAdd(&cnt[dst[ebase + e] - nbase], 1);
    __syncthreads();

    int val = (t < NPG) ? cnt[t] : 0;
    int pc = (val + 7) & ~7;
    int x = pc;
    unsigned m = 0xffffffffu;
    #pragma unroll
    for (int o = 1; o < 32; o <<= 1) {
        int y = __shfl_up_sync(m, x, o);
        if ((t & 31) >= o) x += y;
    }
    if ((t & 31) == 31) ws[t >> 5] = x;
    __syncthreads();
    if (t < 32) {
        int y = ws[t];
        int z = y;
        #pragma unroll
        for (int o = 1; o < 32; o <<= 1) {
            int w = __shfl_up_sync(m, z, o);
            if (t >= o) z += w;
        }
        ws[t] = z - y;
    }
    __syncthreads();
    int excl = x + ws[t >> 5] - pc;
    __syncthreads();

    if (t < NPG) {
        int v = nbase + t;
        g_deg[v]    = val;
        g_rowptr[v] = excl;
        g_dinv[v]   = rsqrtf((float)(val + 1));
        cnt[t] = excl;
    }
    __syncthreads();

    unsigned short* out16 = g_csr16 + (size_t)b * EPAD;
    for (int e = t; e < EPG; e += 1024) {
        int s = src[ebase + e] - nbase;
        int d = dst[ebase + e] - nbase;
        int p = atomicAdd(&cnt[d], 1);
        out16[p] = (unsigned short)s;
    }
}

// ---------------- weight prep: bf16 hi/lo split into swizzled smem images -----
__global__ void k_prepW(const float* __restrict__ Wp, const float* __restrict__ We) {
    int id = blockIdx.x * 256 + threadIdx.x;
    if (id >= DD * DD) return;
    int k = id >> 7, n = id & 127;
    uint32_t off = (uint32_t)k * 256 + (((uint32_t)n * 2) ^ (((uint32_t)k & 7) << 4));

    float w = Wp[id];
    __nv_bfloat16 h = __float2bfloat16(w);
    *(__nv_bfloat16*)(g_Wh_pre + off) = h;
    *(__nv_bfloat16*)(g_Wl_pre + off) = __float2bfloat16(w - __bfloat162float(h));

    w = We[id];
    h = __float2bfloat16(w);
    *(__nv_bfloat16*)(g_Wh_emb + off) = h;
    *(__nv_bfloat16*)(g_Wl_emb + off) = __float2bfloat16(w - __bfloat162float(h));
}

// ---------------- GEMM via mma.sync bf16 (3-term hi/lo), 64-row tiles ---------
// (exact R10 config: 2 CTAs/SM, proven)
__global__ __launch_bounds__(256) void k_gemm_mma(const float* __restrict__ X,
                                                  const char* __restrict__ WhI,
                                                  const char* __restrict__ WlI,
                                                  float* __restrict__ O) {
    extern __shared__ __align__(1024) char smem[];
    char* sXh = smem;                 // 64*256 = 16KB
    char* sXl = smem + 16384;
    char* sWh = smem + 32768;
    char* sWl = smem + 65536;
    int t = threadIdx.x;
    size_t row0 = (size_t)blockIdx.x * 64;

    {
        const int4* s1 = (const int4*)WhI;
        const int4* s2 = (const int4*)WlI;
        int4* d1 = (int4*)sWh;
        int4* d2 = (int4*)sWl;
        #pragma unroll
        for (int i = 0; i < 8; i++) {
            d1[i * 256 + t] = s1[i * 256 + t];
            d2[i * 256 + t] = s2[i * 256 + t];
        }
    }
    {
        const float4* X4 = (const float4*)(X + row0 * DD);
        #pragma unroll
        for (int i = 0; i < 8; i++) {
            int gid = i * 256 + t;
            int r = gid >> 5, c4 = gid & 31;
            float4 v = X4[gid];
            __nv_bfloat16 h0 = __float2bfloat16(v.x), h1 = __float2bfloat16(v.y);
            __nv_bfloat16 h2 = __float2bfloat16(v.z), h3 = __float2bfloat16(v.w);
            __nv_bfloat16 l0 = __float2bfloat16(v.x - __bfloat162float(h0));
            __nv_bfloat16 l1 = __float2bfloat16(v.y - __bfloat162float(h1));
            __nv_bfloat16 l2 = __float2bfloat16(v.z - __bfloat162float(h2));
            __nv_bfloat16 l3 = __float2bfloat16(v.w - __bfloat162float(h3));
            uint32_t off = (uint32_t)r * 256 + (((uint32_t)c4 * 8) ^ (((uint32_t)r & 7) << 4));
            *(uint2*)(sXh + off) = make_uint2(pack_bf16(h0, h1), pack_bf16(h2, h3));
            *(uint2*)(sXl + off) = make_uint2(pack_bf16(l0, l1), pack_bf16(l2, l3));
        }
    }
    __syncthreads();

    int w = t >> 5, lane = t & 31;
    int lr15 = lane & 15;
    uint32_t axor = (uint32_t)(lr15 & 7) << 4;
    uint32_t acolb = (uint32_t)(lane >> 4) * 16;

    uint32_t uXh = smem_u32(sXh), uXl = smem_u32(sXl);
    uint32_t uWh = smem_u32(sWh), uWl = smem_u32(sWl);

    float acc[4][2][4];
    #pragma unroll
    for (int rg = 0; rg < 4; rg++)
        #pragma unroll
        for (int nt = 0; nt < 2; nt++)
            #pragma unroll
            for (int j = 0; j < 4; j++) acc[rg][nt][j] = 0.f;

    #pragma unroll
    for (int kc = 0; kc < 8; kc++) {
        uint32_t bh[2][2], bl[2][2];
        uint32_t brow = (uint32_t)(kc * 16 + lr15) * 256;
        #pragma unroll
        for (int nt = 0; nt < 2; nt++) {
            uint32_t cb = (((uint32_t)w * 32 + (uint32_t)nt * 16) ^ axor);
            ldsm_x2t(bh[nt], uWh + brow + cb);
            ldsm_x2t(bl[nt], uWl + brow + cb);
        }
        uint32_t acb = (((uint32_t)kc * 32 + acolb) ^ axor);
        uint32_t arow = (uint32_t)lr15 * 256;
        #pragma unroll
        for (int rg = 0; rg < 4; rg++) {
            uint32_t ah[4], al[4];
            uint32_t aoff = (uint32_t)rg * 4096 + arow + acb;
            ldsm_x4(ah, uXh + aoff);
            ldsm_x4(al, uXl + aoff);
            #pragma unroll
            for (int nt = 0; nt < 2; nt++) {
                mma16816(acc[rg][nt], ah, bh[nt]);
                mma16816(acc[rg][nt], ah, bl[nt]);
                mma16816(acc[rg][nt], al, bh[nt]);
            }
        }
    }

    int gid = lane >> 2, tig = lane & 3;
    #pragma unroll
    for (int rg = 0; rg < 4; rg++) {
        size_t r0 = row0 + rg * 16 + gid;
        size_t r1 = r0 + 8;
        float dv0 = g_dinv[r0], dv1 = g_dinv[r1];
        #pragma unroll
        for (int nt = 0; nt < 2; nt++) {
            int col = w * 16 + nt * 8 + tig * 2;
            *(float2*)(O + r0 * DD + col) =
                make_float2(dv0 * acc[rg][nt][0], dv0 * acc[rg][nt][1]);
            *(float2*)(O + r1 * DD + col) =
                make_float2(dv1 * acc[rg][nt][2], dv1 * acc[rg][nt][3]);
        }
    }
}

// ---------------- aggregation v5 (smem + u16 edges + f32x2 dual-bank acc) -----
// grid (BBG, 4). smem: s_x [1000][32] floats (125KB) + s_e [24000] u16 (48KB).
// Warp = 4 nodes (sub = lane>>3) x 8 dim-quads (dl = lane&7).
// Inner: 1 LDS.128 index fetch per 8 edges; per edge a ulonglong2 gather +
// 2 packed add.rn.f32x2 into alternating acc banks (chain len /4 vs R11).
__global__ __launch_bounds__(1024, 1) void k_agg(const float* __restrict__ XW,
                                                 float* __restrict__ OUT,
                                                 const float* __restrict__ bias) {
    extern __shared__ __align__(16) char smraw[];
    float* s_x = (float*)smraw;                                     // 128000 B
    unsigned short* s_e = (unsigned short*)(smraw + NPG * 32 * 4);  // 48000 B
    int b = blockIdx.x;
    int q = blockIdx.y;
    int t = threadIdx.x;
    int nbase = b * NPG;

    for (int idx = t; idx < NPG * 8; idx += 1024) {
        int row = idx >> 3;
        int c4 = idx & 7;
        *(float4*)&s_x[row * 32 + c4 * 4] =
            *(const float4*)&XW[(size_t)(nbase + row) * DD + q * 32 + c4 * 4];
    }
    {
        const int4* ge = (const int4*)(g_csr16 + (size_t)b * EPAD);
        int4* se = (int4*)s_e;
        for (int i = t; i < EPAD * 2 / 16; i += 1024) se[i] = ge[i];
    }
    __syncthreads();

    int w = t >> 5, lane = t & 31;
    int sub = lane >> 3;
    int dl = lane & 7;
    float4 bb = *(const float4*)&bias[q * 32 + dl * 4];

    for (int n0 = w * 4; n0 < NPG; n0 += 128) {
        int v = n0 + sub;
        bool valid = (v < NPG);
        int vv = valid ? v : (NPG - 1);
        int cnt = valid ? g_deg[nbase + vv] : 0;
        int start = g_rowptr[nbase + vv];   // local, multiple of 8

        // dual-bank packed accumulators; bank0 init = self-loop term
        unsigned long long a0 = 0ull, a1 = 0ull, b0 = 0ull, b1 = 0ull;
        if (valid) {
            ulonglong2 sv = *(const ulonglong2*)&s_x[vv * 32 + dl * 4];
            a0 = sv.x; a1 = sv.y;
        }

        for (int c = 0; c < cnt; c += 8) {
            uint4 iw = *(const uint4*)&s_e[start + c];   // 8 u16 indices, aligned
            int rem = cnt - c;
            uint32_t parts[4] = {iw.x, iw.y, iw.z, iw.w};
            #pragma unroll
            for (int j = 0; j < 8; j++) {
                int sj = (int)((parts[j >> 1] >> ((j & 1) * 16)) & 0xffffu);
                if (j < rem) {
                    ulonglong2 xs = *(const ulonglong2*)&s_x[sj * 32 + dl * 4];
                    if (j & 1) { add2(b0, xs.x); add2(b1, xs.y); }
                    else       { add2(a0, xs.x); add2(a1, xs.y); }
                }
            }
        }

        if (valid) {
            float2 pa0 = unpack2(a0), pa1 = unpack2(a1);
            float2 pb0 = unpack2(b0), pb1 = unpack2(b1);
            float dv = g_dinv[nbase + v];
            float4 res;
            res.x = fmaxf(dv * (pa0.x + pb0.x) + bb.x, 0.f);
            res.y = fmaxf(dv * (pa0.y + pb0.y) + bb.y, 0.f);
            res.z = fmaxf(dv * (pa1.x + pb1.x) + bb.z, 0.f);
            res.w = fmaxf(dv * (pa1.y + pb1.y) + bb.w, 0.f);
            *(float4*)&OUT[(size_t)(nbase + v) * DD + q * 32 + dl * 4] = res;
        }
    }
}

// ---------------- per-graph mean pool / K ----------------
__global__ void k_pool(const float* __restrict__ NE) {
    int b = blockIdx.x;
    int t = threadIdx.x;
    int dd = t & 127;
    int q = t >> 7;
    const float* base = NE + (size_t)b * NPG * DD + dd;
    float s = 0.f;
    int r0 = q * (NPG / 4);
    #pragma unroll 4
    for (int r = 0; r < NPG / 4; r++) s += base[(size_t)(r0 + r) * DD];
    __shared__ float sm[512];
    sm[t] = s;
    __syncthreads();
    if (q == 0) {
        float tot = sm[dd] + sm[dd + 128] + sm[dd + 256] + sm[dd + 384];
        g_pool[b * DD + dd] = tot * (1.0f / KK);
    }
}

// ---------------- final MLP ----------------
__global__ void k_mlp(const float* __restrict__ W1, const float* __restrict__ b1,
                      const float* __restrict__ W2, const float* __restrict__ b2,
                      float* __restrict__ out) {
    int b = blockIdx.x;
    int t = threadIdx.x;
    __shared__ float p[128], h[128];
    p[t] = g_pool[b * 128 + t];
    __syncthreads();
    float acc = b1[t];
    #pragma unroll 4
    for (int d = 0; d < 128; d++) acc += p[d] * W1[d * 128 + t];
    h[t] = fmaxf(acc, 0.f);
    __syncthreads();
    if (t < 10) {
        float o = b2[t];
        #pragma unroll 4
        for (int j = 0; j < 128; j++) o += h[j] * W2[j * 10 + t];
        out[b * 10 + t] = o;
    }
}

// ---------------- launch ----------------
extern "C" void kernel_launch(void* const* d_in, const int* in_sizes, int n_in,
                              void* d_out, int out_size) {
    const float* x     = (const float*)d_in[0];
    const int*   ei    = (const int*)d_in[1];
    const float* W_pre = (const float*)d_in[3];
    const float* b_pre = (const float*)d_in[4];
    const float* W_emb = (const float*)d_in[5];
    const float* b_emb = (const float*)d_in[6];
    // d_in[2] batch, d_in[7] W_asn, d_in[8] b_asn dead (softmax rows sum to 1)
    const float* W1 = (const float*)d_in[9];
    const float* b1 = (const float*)d_in[10];
    const float* W2 = (const float*)d_in[11];
    const float* b2 = (const float*)d_in[12];
    float* out = (float*)d_out;

    int E = in_sizes[1] / 2;
    int N = in_sizes[0] / DD;
    const int* src = ei;
    const int* dst = ei + E;

    void *pA, *pB, *pWhp, *pWlp, *pWhe, *pWle;
    cudaGetSymbolAddress(&pA, g_bufA);
    cudaGetSymbolAddress(&pB, g_bufB);
    cudaGetSymbolAddress(&pWhp, g_Wh_pre);
    cudaGetSymbolAddress(&pWlp, g_Wl_pre);
    cudaGetSymbolAddress(&pWhe, g_Wh_emb);
    cudaGetSymbolAddress(&pWle, g_Wl_emb);
    float* bufA = (float*)pA;
    float* bufB = (float*)pB;

    const int smem_mma = 98304;                                   // 96KB, 2 CTAs/SM
    const int smem_agg = NPG * 32 * 4 + EPAD * 2;                 // 176000B
    cudaFuncSetAttribute(k_gemm_mma, cudaFuncAttributeMaxDynamicSharedMemorySize, smem_mma);
    cudaFuncSetAttribute(k_agg, cudaFuncAttributeMaxDynamicSharedMemorySize, smem_agg);

    // padded u16 CSR build + weight bf16 hi/lo swizzled images
    k_build<<<BBG, 1024>>>(src, dst);
    k_prepW<<<64, 256>>>(W_pre, W_emb);

    // conv1: h = relu(Ahat @ (x @ W_pre) + b_pre)   [dinv folded into GEMM rows]
    k_gemm_mma<<<N / 64, 256, smem_mma>>>(x, (const char*)pWhp, (const char*)pWlp, bufA);
    k_agg<<<dim3(BBG, 4), 1024, smem_agg>>>(bufA, bufB, b_pre);

    // conv2: NE = relu(Ahat @ (h @ W_emb) + b_emb)
    k_gemm_mma<<<N / 64, 256, smem_mma>>>(bufB, (const char*)pWhe, (const char*)pWle, bufA);
    k_agg<<<dim3(BBG, 4), 1024, smem_agg>>>(bufA, bufB, b_emb);

    // pool (assignment branch collapses to mean/K) + MLP head
    k_pool<<<BBG, 512>>>(bufB);
    k_mlp<<<BBG, 128>>>(W1, b1, W2, b2, out);
}

// round 13
// speedup vs baseline: 1.1140x; 1.1140x over previous
#include <cuda_runtime.h>
#include <cuda_bf16.h>
#include <math.h>
#include <stdint.h>

#define NN  128000   // B*NPG nodes
#define EE  2048000  // B*EPG edges
#define BBG 128      // graphs
#define NPG 1000
#define EPG 16000
#define DD  128
#define KK  64
#define EPAD 24000   // padded per-graph CSR capacity

// ---------------- scratch (static device globals; no allocs) ----------------
__device__ int      g_deg[NN];
__device__ float    g_dinv[NN];
__device__ int      g_rowptr[NN];              // graph-LOCAL padded CSR offset (mult of 8)
__device__ unsigned short g_csr16[BBG * EPAD]; // graph-local src index per edge
__device__ float    g_bufA[(size_t)NN * DD];
__device__ float    g_bufB[(size_t)NN * DD];
__device__ float    g_pool[BBG * DD];
// bf16 hi/lo weight images, PRE-SWIZZLED into the exact smem byte layout
__device__ char  g_Wh_pre[32768];
__device__ char  g_Wl_pre[32768];
__device__ char  g_Wh_emb[32768];
__device__ char  g_Wl_emb[32768];

// ---------------- warp-MMA helpers (base ISA; proven R9-R11) ------------------
__device__ __forceinline__ uint32_t smem_u32(const void* p) {
    uint32_t a;
    asm("{ .reg .u64 t; cvta.to.shared.u64 t, %1; cvt.u32.u64 %0, t; }" : "=r"(a) : "l"(p));
    return a;
}
__device__ __forceinline__ void ldsm_x4(uint32_t* r, uint32_t a) {
    asm volatile("ldmatrix.sync.aligned.m8n8.x4.shared.b16 {%0,%1,%2,%3}, [%4];"
                 : "=r"(r[0]), "=r"(r[1]), "=r"(r[2]), "=r"(r[3]) : "r"(a));
}
__device__ __forceinline__ void ldsm_x2t(uint32_t* r, uint32_t a) {
    asm volatile("ldmatrix.sync.aligned.m8n8.x2.trans.shared.b16 {%0,%1}, [%2];"
                 : "=r"(r[0]), "=r"(r[1]) : "r"(a));
}
__device__ __forceinline__ void mma16816(float* d, const uint32_t* a, const uint32_t* b) {
    asm volatile("mma.sync.aligned.m16n8k16.row.col.f32.bf16.bf16.f32 "
                 "{%0,%1,%2,%3}, {%4,%5,%6,%7}, {%8,%9}, {%0,%1,%2,%3};"
                 : "+f"(d[0]), "+f"(d[1]), "+f"(d[2]), "+f"(d[3])
                 : "r"(a[0]), "r"(a[1]), "r"(a[2]), "r"(a[3]), "r"(b[0]), "r"(b[1]));
}
__device__ __forceinline__ uint32_t pack_bf16(__nv_bfloat16 lo, __nv_bfloat16 hi) {
    return ((uint32_t)__bfloat16_as_ushort(hi) << 16) | __bfloat16_as_ushort(lo);
}

// ---------------- degree + dinv (needed by GEMM1 epilogue) --------------------
__global__ __launch_bounds__(1024) void k_deg(const int* __restrict__ dst) {
    __shared__ int cnt[NPG];
    int b = blockIdx.x, t = threadIdx.x;
    int ebase = b * EPG, nbase = b * NPG;
    if (t < NPG) cnt[t] = 0;
    __syncthreads();
    for (int e = t; e < EPG; e += 1024)
        atomicAdd(&cnt[dst[ebase + e] - nbase], 1);
    __syncthreads();
    if (t < NPG) {
        int val = cnt[t];
        g_deg[nbase + t]  = val;
        g_dinv[nbase + t] = rsqrtf((float)(val + 1));  // +1 self-loop
    }
}

// ---------------- CSR fill (scan + scatter; overlaps GEMM1 on stream 2) -------
__global__ __launch_bounds__(1024) void k_fill(const int* __restrict__ src,
                                               const int* __restrict__ dst) {
    __shared__ int cnt[NPG];
    __shared__ int ws[32];
    int b = blockIdx.x, t = threadIdx.x;
    int ebase = b * EPG, nbase = b * NPG;

    int val = (t < NPG) ? g_deg[nbase + t] : 0;
    int pc = (val + 7) & ~7;            // padded to multiple of 8
    int x = pc;
    unsigned m = 0xffffffffu;
    #pragma unroll
    for (int o = 1; o < 32; o <<= 1) {
        int y = __shfl_up_sync(m, x, o);
        if ((t & 31) >= o) x += y;
    }
    if ((t & 31) == 31) ws[t >> 5] = x;
    __syncthreads();
    if (t < 32) {
        int y = ws[t];
        int z = y;
        #pragma unroll
        for (int o = 1; o < 32; o <<= 1) {
            int w = __shfl_up_sync(m, z, o);
            if (t >= o) z += w;
        }
        ws[t] = z - y;
    }
    __syncthreads();
    int excl = x + ws[t >> 5] - pc;
    __syncthreads();

    if (t < NPG) {
        g_rowptr[nbase + t] = excl;     // LOCAL padded offset (mult of 8)
        cnt[t] = excl;                  // cursor
    }
    __syncthreads();

    unsigned short* out16 = g_csr16 + (size_t)b * EPAD;
    for (int e = t; e < EPG; e += 1024) {
        int s = src[ebase + e] - nbase;
        int d = dst[ebase + e] - nbase;
        int p = atomicAdd(&cnt[d], 1);
        out16[p] = (unsigned short)s;
    }
}

// ---------------- weight prep: bf16 hi/lo split into swizzled smem images -----
__global__ void k_prepW(const float* __restrict__ Wp, const float* __restrict__ We) {
    int id = blockIdx.x * 256 + threadIdx.x;
    if (id >= DD * DD) return;
    int k = id >> 7, n = id & 127;
    uint32_t off = (uint32_t)k * 256 + (((uint32_t)n * 2) ^ (((uint32_t)k & 7) << 4));

    float w = Wp[id];
    __nv_bfloat16 h = __float2bfloat16(w);
    *(__nv_bfloat16*)(g_Wh_pre + off) = h;
    *(__nv_bfloat16*)(g_Wl_pre + off) = __float2bfloat16(w - __bfloat162float(h));

    w = We[id];
    h = __float2bfloat16(w);
    *(__nv_bfloat16*)(g_Wh_emb + off) = h;
    *(__nv_bfloat16*)(g_Wl_emb + off) = __float2bfloat16(w - __bfloat162float(h));
}

// ---------------- GEMM via mma.sync bf16 (3-term hi/lo), 64-row tiles ---------
// (exact R10 config: 2 CTAs/SM, proven)
__global__ __launch_bounds__(256) void k_gemm_mma(const float* __restrict__ X,
                                                  const char* __restrict__ WhI,
                                                  const char* __restrict__ WlI,
                                                  float* __restrict__ O) {
    extern __shared__ __align__(1024) char smem[];
    char* sXh = smem;                 // 64*256 = 16KB
    char* sXl = smem + 16384;
    char* sWh = smem + 32768;
    char* sWl = smem + 65536;
    int t = threadIdx.x;
    size_t row0 = (size_t)blockIdx.x * 64;

    {
        const int4* s1 = (const int4*)WhI;
        const int4* s2 = (const int4*)WlI;
        int4* d1 = (int4*)sWh;
        int4* d2 = (int4*)sWl;
        #pragma unroll
        for (int i = 0; i < 8; i++) {
            d1[i * 256 + t] = s1[i * 256 + t];
            d2[i * 256 + t] = s2[i * 256 + t];
        }
    }
    {
        const float4* X4 = (const float4*)(X + row0 * DD);
        #pragma unroll
        for (int i = 0; i < 8; i++) {
            int gid = i * 256 + t;
            int r = gid >> 5, c4 = gid & 31;
            float4 v = X4[gid];
            __nv_bfloat16 h0 = __float2bfloat16(v.x), h1 = __float2bfloat16(v.y);
            __nv_bfloat16 h2 = __float2bfloat16(v.z), h3 = __float2bfloat16(v.w);
            __nv_bfloat16 l0 = __float2bfloat16(v.x - __bfloat162float(h0));
            __nv_bfloat16 l1 = __float2bfloat16(v.y - __bfloat162float(h1));
            __nv_bfloat16 l2 = __float2bfloat16(v.z - __bfloat162float(h2));
            __nv_bfloat16 l3 = __float2bfloat16(v.w - __bfloat162float(h3));
            uint32_t off = (uint32_t)r * 256 + (((uint32_t)c4 * 8) ^ (((uint32_t)r & 7) << 4));
            *(uint2*)(sXh + off) = make_uint2(pack_bf16(h0, h1), pack_bf16(h2, h3));
            *(uint2*)(sXl + off) = make_uint2(pack_bf16(l0, l1), pack_bf16(l2, l3));
        }
    }
    __syncthreads();

    int w = t >> 5, lane = t & 31;
    int lr15 = lane & 15;
    uint32_t axor = (uint32_t)(lr15 & 7) << 4;
    uint32_t acolb = (uint32_t)(lane >> 4) * 16;

    uint32_t uXh = smem_u32(sXh), uXl = smem_u32(sXl);
    uint32_t uWh = smem_u32(sWh), uWl = smem_u32(sWl);

    float acc[4][2][4];
    #pragma unroll
    for (int rg = 0; rg < 4; rg++)
        #pragma unroll
        for (int nt = 0; nt < 2; nt++)
            #pragma unroll
            for (int j = 0; j < 4; j++) acc[rg][nt][j] = 0.f;

    #pragma unroll
    for (int kc = 0; kc < 8; kc++) {
        uint32_t bh[2][2], bl[2][2];
        uint32_t brow = (uint32_t)(kc * 16 + lr15) * 256;
        #pragma unroll
        for (int nt = 0; nt < 2; nt++) {
            uint32_t cb = (((uint32_t)w * 32 + (uint32_t)nt * 16) ^ axor);
            ldsm_x2t(bh[nt], uWh + brow + cb);
            ldsm_x2t(bl[nt], uWl + brow + cb);
        }
        uint32_t acb = (((uint32_t)kc * 32 + acolb) ^ axor);
        uint32_t arow = (uint32_t)lr15 * 256;
        #pragma unroll
        for (int rg = 0; rg < 4; rg++) {
            uint32_t ah[4], al[4];
            uint32_t aoff = (uint32_t)rg * 4096 + arow + acb;
            ldsm_x4(ah, uXh + aoff);
            ldsm_x4(al, uXl + aoff);
            #pragma unroll
            for (int nt = 0; nt < 2; nt++) {
                mma16816(acc[rg][nt], ah, bh[nt]);
                mma16816(acc[rg][nt], ah, bl[nt]);
                mma16816(acc[rg][nt], al, bh[nt]);
            }
        }
    }

    int gid = lane >> 2, tig = lane & 3;
    #pragma unroll
    for (int rg = 0; rg < 4; rg++) {
        size_t r0 = row0 + rg * 16 + gid;
        size_t r1 = r0 + 8;
        float dv0 = g_dinv[r0], dv1 = g_dinv[r1];
        #pragma unroll
        for (int nt = 0; nt < 2; nt++) {
            int col = w * 16 + nt * 8 + tig * 2;
            *(float2*)(O + r0 * DD + col) =
                make_float2(dv0 * acc[rg][nt][0], dv0 * acc[rg][nt][1]);
            *(float2*)(O + r1 * DD + col) =
                make_float2(dv1 * acc[rg][nt][2], dv1 * acc[rg][nt][3]);
        }
    }
}

// ---------------- aggregation (R11-proven inner; optional fused mean-pool) ----
// grid (BBG, 4). smem: s_x [1000][32] (125KB) + s_e [24000] u16 (48KB) +
// warp-sum scratch (4KB). Warp = 4 nodes (sub) x 8 dim-quads (dl).
// pool == nullptr: write OUT rows (conv1). pool != nullptr: skip all global
// stores, reduce relu-activations to per-dim sums -> g_pool (conv2; the
// mean-pool is the ONLY consumer of conv2's output).
__global__ __launch_bounds__(1024, 1) void k_agg(const float* __restrict__ XW,
                                                 float* __restrict__ OUT,
                                                 const float* __restrict__ bias,
                                                 float* __restrict__ pool) {
    extern __shared__ __align__(16) char smraw[];
    float* s_x = (float*)smraw;                                     // 128000 B
    unsigned short* s_e = (unsigned short*)(smraw + NPG * 32 * 4);  // 48000 B
    float* s_ws = (float*)(smraw + NPG * 32 * 4 + EPAD * 2);        // 4096 B
    int b = blockIdx.x;
    int q = blockIdx.y;
    int t = threadIdx.x;
    int nbase = b * NPG;

    for (int idx = t; idx < NPG * 8; idx += 1024) {
        int row = idx >> 3;
        int c4 = idx & 7;
        *(float4*)&s_x[row * 32 + c4 * 4] =
            *(const float4*)&XW[(size_t)(nbase + row) * DD + q * 32 + c4 * 4];
    }
    {
        const int4* ge = (const int4*)(g_csr16 + (size_t)b * EPAD);
        int4* se = (int4*)s_e;
        for (int i = t; i < EPAD * 2 / 16; i += 1024) se[i] = ge[i];
    }
    __syncthreads();

    int w = t >> 5, lane = t & 31;
    int sub = lane >> 3;
    int dl = lane & 7;
    float4 bb = *(const float4*)&bias[q * 32 + dl * 4];
    float4 psum = make_float4(0.f, 0.f, 0.f, 0.f);

    for (int n0 = w * 4; n0 < NPG; n0 += 128) {
        int v = n0 + sub;
        bool valid = (v < NPG);
        int vv = valid ? v : (NPG - 1);
        int cnt = valid ? g_deg[nbase + vv] : 0;
        int start = g_rowptr[nbase + vv];   // local, multiple of 8

        float4 acc = make_float4(0.f, 0.f, 0.f, 0.f);
        if (valid) acc = *(const float4*)&s_x[vv * 32 + dl * 4];  // self-loop

        for (int c = 0; c < cnt; c += 8) {
            uint4 iw = *(const uint4*)&s_e[start + c];   // 8 u16 indices, aligned
            int rem = cnt - c;
            uint32_t parts[4] = {iw.x, iw.y, iw.z, iw.w};
            #pragma unroll
            for (int j = 0; j < 8; j++) {
                int sj = (int)((parts[j >> 1] >> ((j & 1) * 16)) & 0xffffu);
                if (j < rem) {
                    float4 xs = *(const float4*)&s_x[sj * 32 + dl * 4];
                    acc.x += xs.x; acc.y += xs.y; acc.z += xs.z; acc.w += xs.w;
                }
            }
        }

        if (valid) {
            float dv = g_dinv[nbase + v];
            float4 res = make_float4(fmaxf(dv * acc.x + bb.x, 0.f),
                                     fmaxf(dv * acc.y + bb.y, 0.f),
                                     fmaxf(dv * acc.z + bb.z, 0.f),
                                     fmaxf(dv * acc.w + bb.w, 0.f));
            if (pool) {
                psum.x += res.x; psum.y += res.y; psum.z += res.z; psum.w += res.w;
            } else {
                *(float4*)&OUT[(size_t)(nbase + v) * DD + q * 32 + dl * 4] = res;
            }
        }
    }

    if (pool) {
        unsigned mm = 0xffffffffu;
        psum.x += __shfl_down_sync(mm, psum.x, 16);
        psum.y += __shfl_down_sync(mm, psum.y, 16);
        psum.z += __shfl_down_sync(mm, psum.z, 16);
        psum.w += __shfl_down_sync(mm, psum.w, 16);
        psum.x += __shfl_down_sync(mm, psum.x, 8);
        psum.y += __shfl_down_sync(mm, psum.y, 8);
        psum.z += __shfl_down_sync(mm, psum.z, 8);
        psum.w += __shfl_down_sync(mm, psum.w, 8);
        if (lane < 8) *(float4*)&s_ws[w * 32 + lane * 4] = psum;
        __syncthreads();
        if (t < 32) {
            float sum = 0.f;
            #pragma unroll 8
            for (int ww = 0; ww < 32; ww++) sum += s_ws[ww * 32 + t];
            pool[b * DD + q * 32 + t] = sum * (1.0f / KK);
        }
    }
}

// ---------------- final MLP ----------------
__global__ void k_mlp(const float* __restrict__ W1, const float* __restrict__ b1,
                      const float* __restrict__ W2, const float* __restrict__ b2,
                      float* __restrict__ out) {
    int b = blockIdx.x;
    int t = threadIdx.x;
    __shared__ float p[128], h[128];
    p[t] = g_pool[b * 128 + t];
    __syncthreads();
    float acc = b1[t];
    #pragma unroll 4
    for (int d = 0; d < 128; d++) acc += p[d] * W1[d * 128 + t];
    h[t] = fmaxf(acc, 0.f);
    __syncthreads();
    if (t < 10) {
        float o = b2[t];
        #pragma unroll 4
        for (int j = 0; j < 128; j++) o += h[j] * W2[j * 10 + t];
        out[b * 10 + t] = o;
    }
}

// ---------------- launch ----------------
extern "C" void kernel_launch(void* const* d_in, const int* in_sizes, int n_in,
                              void* d_out, int out_size) {
    const float* x     = (const float*)d_in[0];
    const int*   ei    = (const int*)d_in[1];
    const float* W_pre = (const float*)d_in[3];
    const float* b_pre = (const float*)d_in[4];
    const float* W_emb = (const float*)d_in[5];
    const float* b_emb = (const float*)d_in[6];
    // d_in[2] batch, d_in[7] W_asn, d_in[8] b_asn dead (softmax rows sum to 1)
    const float* W1 = (const float*)d_in[9];
    const float* b1 = (const float*)d_in[10];
    const float* W2 = (const float*)d_in[11];
    const float* b2 = (const float*)d_in[12];
    float* out = (float*)d_out;

    int E = in_sizes[1] / 2;
    int N = in_sizes[0] / DD;
    const int* src = ei;
    const int* dst = ei + E;

    void *pA, *pB, *pP, *pWhp, *pWlp, *pWhe, *pWle;
    cudaGetSymbolAddress(&pA, g_bufA);
    cudaGetSymbolAddress(&pB, g_bufB);
    cudaGetSymbolAddress(&pP, g_pool);
    cudaGetSymbolAddress(&pWhp, g_Wh_pre);
    cudaGetSymbolAddress(&pWlp, g_Wl_pre);
    cudaGetSymbolAddress(&pWhe, g_Wh_emb);
    cudaGetSymbolAddress(&pWle, g_Wl_emb);
    float* bufA = (float*)pA;
    float* bufB = (float*)pB;

    const int smem_mma = 98304;                                   // 96KB, 2 CTAs/SM
    const int smem_agg = NPG * 32 * 4 + EPAD * 2 + 4096;          // 180096B
    cudaFuncSetAttribute(k_gemm_mma, cudaFuncAttributeMaxDynamicSharedMemorySize, smem_mma);
    cudaFuncSetAttribute(k_agg, cudaFuncAttributeMaxDynamicSharedMemorySize, smem_agg);

    // side stream + events for fork-join (lazy init; host resources only)
    static cudaStream_t s2 = 0;
    static cudaEvent_t evFork = 0, evJoin = 0;
    if (!s2) {
        cudaStreamCreateWithFlags(&s2, cudaStreamNonBlocking);
        cudaEventCreateWithFlags(&evFork, cudaEventDisableTiming);
        cudaEventCreateWithFlags(&evJoin, cudaEventDisableTiming);
    }

    // serial prerequisites of GEMM1: weight images + dinv
    k_prepW<<<64, 256>>>(W_pre, W_emb);
    k_deg<<<BBG, 1024>>>(dst);

    // fork: CSR fill (needed only by agg1) overlaps GEMM1
    cudaEventRecord(evFork, 0);
    cudaStreamWaitEvent(s2, evFork, 0);
    k_fill<<<BBG, 1024, 0, s2>>>(src, dst);
    cudaEventRecord(evJoin, s2);

    // conv1: h = relu(Ahat @ (x @ W_pre) + b_pre)   [dinv folded into GEMM rows]
    k_gemm_mma<<<N / 64, 256, smem_mma>>>(x, (const char*)pWhp, (const char*)pWlp, bufA);
    cudaStreamWaitEvent(0, evJoin, 0);   // join before aggregation
    k_agg<<<dim3(BBG, 4), 1024, smem_agg>>>(bufA, bufB, b_pre, nullptr);

    // conv2: NE = relu(Ahat @ (h @ W_emb) + b_emb); mean-pool fused into agg
    k_gemm_mma<<<N / 64, 256, smem_mma>>>(bufB, (const char*)pWhe, (const char*)pWle, bufA);
    k_agg<<<dim3(BBG, 4), 1024, smem_agg>>>(bufA, bufB, b_emb, (float*)pP);

    // MLP head
    k_mlp<<<BBG, 128>>>(W1, b1, W2, b2, out);
}

// round 15
// speedup vs baseline: 1.2204x; 1.0955x over previous
#include <cuda_runtime.h>
#include <cuda_bf16.h>
#include <math.h>
#include <stdint.h>

#define NN  128000   // B*NPG nodes
#define EE  2048000  // B*EPG edges
#define BBG 128      // graphs
#define NPG 1000
#define EPG 16000
#define DD  128
#define KK  64
#define EPAD 24000   // padded per-graph CSR capacity

// ---------------- scratch (static device globals; no allocs) ----------------
__device__ int      g_deg[NN];
__device__ float    g_dinv[NN];
__device__ int      g_rowptr[NN];              // graph-LOCAL padded CSR offset (mult of 8)
__device__ unsigned short g_csr16[BBG * EPAD]; // graph-local src index per edge
__device__ unsigned short g_perm[NN];          // degree-sorted node permutation (local)
__device__ float    g_bufA[(size_t)NN * DD];
__device__ float    g_bufB[(size_t)NN * DD];
__device__ float    g_pool[BBG * DD];
// bf16 hi/lo weight images, PRE-SWIZZLED into the exact smem byte layout
__device__ char  g_Wh_pre[32768];
__device__ char  g_Wl_pre[32768];
__device__ char  g_Wh_emb[32768];
__device__ char  g_Wl_emb[32768];

// ---------------- warp-MMA helpers (base ISA; proven R9-R13) ------------------
__device__ __forceinline__ uint32_t smem_u32(const void* p) {
    uint32_t a;
    asm("{ .reg .u64 t; cvta.to.shared.u64 t, %1; cvt.u32.u64 %0, t; }" : "=r"(a) : "l"(p));
    return a;
}
__device__ __forceinline__ void ldsm_x4(uint32_t* r, uint32_t a) {
    asm volatile("ldmatrix.sync.aligned.m8n8.x4.shared.b16 {%0,%1,%2,%3}, [%4];"
                 : "=r"(r[0]), "=r"(r[1]), "=r"(r[2]), "=r"(r[3]) : "r"(a));
}
__device__ __forceinline__ void ldsm_x2t(uint32_t* r, uint32_t a) {
    asm volatile("ldmatrix.sync.aligned.m8n8.x2.trans.shared.b16 {%0,%1}, [%2];"
                 : "=r"(r[0]), "=r"(r[1]) : "r"(a));
}
__device__ __forceinline__ void mma16816(float* d, const uint32_t* a, const uint32_t* b) {
    asm volatile("mma.sync.aligned.m16n8k16.row.col.f32.bf16.bf16.f32 "
                 "{%0,%1,%2,%3}, {%4,%5,%6,%7}, {%8,%9}, {%0,%1,%2,%3};"
                 : "+f"(d[0]), "+f"(d[1]), "+f"(d[2]), "+f"(d[3])
                 : "r"(a[0]), "r"(a[1]), "r"(a[2]), "r"(a[3]), "r"(b[0]), "r"(b[1]));
}
__device__ __forceinline__ uint32_t pack_bf16(__nv_bfloat16 lo, __nv_bfloat16 hi) {
    return ((uint32_t)__bfloat16_as_ushort(hi) << 16) | __bfloat16_as_ushort(lo);
}

// ---------------- degree + dinv (needed by GEMM1 epilogue) --------------------
__global__ __launch_bounds__(1024) void k_deg(const int* __restrict__ dst) {
    __shared__ int cnt[NPG];
    int b = blockIdx.x, t = threadIdx.x;
    int ebase = b * EPG, nbase = b * NPG;
    if (t < NPG) cnt[t] = 0;
    __syncthreads();
    for (int e = t; e < EPG; e += 1024)
        atomicAdd(&cnt[dst[ebase + e] - nbase], 1);
    __syncthreads();
    if (t < NPG) {
        int val = cnt[t];
        g_deg[nbase + t]  = val;
        g_dinv[nbase + t] = rsqrtf((float)(val + 1));  // +1 self-loop
    }
}

// ---------------- CSR fill + degree-sorted permutation (overlaps GEMM1) -------
__global__ __launch_bounds__(1024) void k_fill(const int* __restrict__ src,
                                               const int* __restrict__ dst) {
    __shared__ int cnt[NPG];
    __shared__ int ws[32];
    __shared__ int bcnt[64];
    __shared__ int bstart[64];
    int b = blockIdx.x, t = threadIdx.x;
    int ebase = b * EPG, nbase = b * NPG;

    int val = (t < NPG) ? g_deg[nbase + t] : 0;
    int pc = (val + 7) & ~7;            // padded to multiple of 8
    int x = pc;
    unsigned m = 0xffffffffu;
    #pragma unroll
    for (int o = 1; o < 32; o <<= 1) {
        int y = __shfl_up_sync(m, x, o);
        if ((t & 31) >= o) x += y;
    }
    if ((t & 31) == 31) ws[t >> 5] = x;
    if (t < 64) bcnt[t] = 0;
    __syncthreads();
    if (t < 32) {
        int y = ws[t];
        int z = y;
        #pragma unroll
        for (int o = 1; o < 32; o <<= 1) {
            int w = __shfl_up_sync(m, z, o);
            if (t >= o) z += w;
        }
        ws[t] = z - y;
    }
    __syncthreads();
    int excl = x + ws[t >> 5] - pc;
    __syncthreads();

    // degree-bucket rank (counting sort, 64 buckets)
    int mybkt = min(val, 63);
    int brank = 0;
    if (t < NPG) {
        g_rowptr[nbase + t] = excl;     // LOCAL padded offset (mult of 8)
        cnt[t] = excl;                  // cursor
        brank = atomicAdd(&bcnt[mybkt], 1);
    }
    __syncthreads();
    if (t == 0) {
        int s = 0;
        #pragma unroll
        for (int i = 0; i < 64; i++) { bstart[i] = s; s += bcnt[i]; }
    }
    __syncthreads();
    if (t < NPG)
        g_perm[nbase + bstart[mybkt] + brank] = (unsigned short)t;

    unsigned short* out16 = g_csr16 + (size_t)b * EPAD;
    for (int e = t; e < EPG; e += 1024) {
        int s = src[ebase + e] - nbase;
        int d = dst[ebase + e] - nbase;
        int p = atomicAdd(&cnt[d], 1);
        out16[p] = (unsigned short)s;
    }
}

// ---------------- weight prep: bf16 hi/lo split into swizzled smem images -----
__global__ void k_prepW(const float* __restrict__ Wp, const float* __restrict__ We) {
    int id = blockIdx.x * 256 + threadIdx.x;
    if (id >= DD * DD) return;
    int k = id >> 7, n = id & 127;
    uint32_t off = (uint32_t)k * 256 + (((uint32_t)n * 2) ^ (((uint32_t)k & 7) << 4));

    float w = Wp[id];
    __nv_bfloat16 h = __float2bfloat16(w);
    *(__nv_bfloat16*)(g_Wh_pre + off) = h;
    *(__nv_bfloat16*)(g_Wl_pre + off) = __float2bfloat16(w - __bfloat162float(h));

    w = We[id];
    h = __float2bfloat16(w);
    *(__nv_bfloat16*)(g_Wh_emb + off) = h;
    *(__nv_bfloat16*)(g_Wl_emb + off) = __float2bfloat16(w - __bfloat162float(h));
}

// ---------------- GEMM via mma.sync bf16 (3-term hi/lo), 64-row tiles ---------
// (exact R10/R13 config: 2 CTAs/SM, proven)
__global__ __launch_bounds__(256) void k_gemm_mma(const float* __restrict__ X,
                                                  const char* __restrict__ WhI,
                                                  const char* __restrict__ WlI,
                                                  float* __restrict__ O) {
    extern __shared__ __align__(1024) char smem[];
    char* sXh = smem;                 // 64*256 = 16KB
    char* sXl = smem + 16384;
    char* sWh = smem + 32768;
    char* sWl = smem + 65536;
    int t = threadIdx.x;
    size_t row0 = (size_t)blockIdx.x * 64;

    {
        const int4* s1 = (const int4*)WhI;
        const int4* s2 = (const int4*)WlI;
        int4* d1 = (int4*)sWh;
        int4* d2 = (int4*)sWl;
        #pragma unroll
        for (int i = 0; i < 8; i++) {
            d1[i * 256 + t] = s1[i * 256 + t];
            d2[i * 256 + t] = s2[i * 256 + t];
        }
    }
    {
        const float4* X4 = (const float4*)(X + row0 * DD);
        #pragma unroll
        for (int i = 0; i < 8; i++) {
            int gid = i * 256 + t;
            int r = gid >> 5, c4 = gid & 31;
            float4 v = X4[gid];
            __nv_bfloat16 h0 = __float2bfloat16(v.x), h1 = __float2bfloat16(v.y);
            __nv_bfloat16 h2 = __float2bfloat16(v.z), h3 = __float2bfloat16(v.w);
            __nv_bfloat16 l0 = __float2bfloat16(v.x - __bfloat162float(h0));
            __nv_bfloat16 l1 = __float2bfloat16(v.y - __bfloat162float(h1));
            __nv_bfloat16 l2 = __float2bfloat16(v.z - __bfloat162float(h2));
            __nv_bfloat16 l3 = __float2bfloat16(v.w - __bfloat162float(h3));
            uint32_t off = (uint32_t)r * 256 + (((uint32_t)c4 * 8) ^ (((uint32_t)r & 7) << 4));
            *(uint2*)(sXh + off) = make_uint2(pack_bf16(h0, h1), pack_bf16(h2, h3));
            *(uint2*)(sXl + off) = make_uint2(pack_bf16(l0, l1), pack_bf16(l2, l3));
        }
    }
    __syncthreads();

    int w = t >> 5, lane = t & 31;
    int lr15 = lane & 15;
    uint32_t axor = (uint32_t)(lr15 & 7) << 4;
    uint32_t acolb = (uint32_t)(lane >> 4) * 16;

    uint32_t uXh = smem_u32(sXh), uXl = smem_u32(sXl);
    uint32_t uWh = smem_u32(sWh), uWl = smem_u32(sWl);

    float acc[4][2][4];
    #pragma unroll
    for (int rg = 0; rg < 4; rg++)
        #pragma unroll
        for (int nt = 0; nt < 2; nt++)
            #pragma unroll
            for (int j = 0; j < 4; j++) acc[rg][nt][j] = 0.f;

    #pragma unroll
    for (int kc = 0; kc < 8; kc++) {
        uint32_t bh[2][2], bl[2][2];
        uint32_t brow = (uint32_t)(kc * 16 + lr15) * 256;
        #pragma unroll
        for (int nt = 0; nt < 2; nt++) {
            uint32_t cb = (((uint32_t)w * 32 + (uint32_t)nt * 16) ^ axor);
            ldsm_x2t(bh[nt], uWh + brow + cb);
            ldsm_x2t(bl[nt], uWl + brow + cb);
        }
        uint32_t acb = (((uint32_t)kc * 32 + acolb) ^ axor);
        uint32_t arow = (uint32_t)lr15 * 256;
        #pragma unroll
        for (int rg = 0; rg < 4; rg++) {
            uint32_t ah[4], al[4];
            uint32_t aoff = (uint32_t)rg * 4096 + arow + acb;
            ldsm_x4(ah, uXh + aoff);
            ldsm_x4(al, uXl + aoff);
            #pragma unroll
            for (int nt = 0; nt < 2; nt++) {
                mma16816(acc[rg][nt], ah, bh[nt]);
                mma16816(acc[rg][nt], ah, bl[nt]);
                mma16816(acc[rg][nt], al, bh[nt]);
            }
        }
    }

    int gid = lane >> 2, tig = lane & 3;
    #pragma unroll
    for (int rg = 0; rg < 4; rg++) {
        size_t r0 = row0 + rg * 16 + gid;
        size_t r1 = r0 + 8;
        float dv0 = g_dinv[r0], dv1 = g_dinv[r1];
        #pragma unroll
        for (int nt = 0; nt < 2; nt++) {
            int col = w * 16 + nt * 8 + tig * 2;
            *(float2*)(O + r0 * DD + col) =
                make_float2(dv0 * acc[rg][nt][0], dv0 * acc[rg][nt][1]);
            *(float2*)(O + r1 * DD + col) =
                make_float2(dv1 * acc[rg][nt][2], dv1 * acc[rg][nt][3]);
        }
    }
}

// ---------------- aggregation (R11 inner + degree-sorted nodes + fused pool) --
__global__ __launch_bounds__(1024, 1) void k_agg(const float* __restrict__ XW,
                                                 float* __restrict__ OUT,
                                                 const float* __restrict__ bias,
                                                 float* __restrict__ pool) {
    extern __shared__ __align__(16) char smraw[];
    float* s_x = (float*)smraw;                                     // 128000 B
    unsigned short* s_e = (unsigned short*)(smraw + NPG * 32 * 4);  // 48000 B
    float* s_ws = (float*)(smraw + NPG * 32 * 4 + EPAD * 2);        // 4096 B
    unsigned short* s_p = (unsigned short*)(smraw + NPG * 32 * 4 + EPAD * 2 + 4096); // 2000 B
    int b = blockIdx.x;
    int q = blockIdx.y;
    int t = threadIdx.x;
    int nbase = b * NPG;

    for (int idx = t; idx < NPG * 8; idx += 1024) {
        int row = idx >> 3;
        int c4 = idx & 7;
        *(float4*)&s_x[row * 32 + c4 * 4] =
            *(const float4*)&XW[(size_t)(nbase + row) * DD + q * 32 + c4 * 4];
    }
    {
        const int4* ge = (const int4*)(g_csr16 + (size_t)b * EPAD);
        int4* se = (int4*)s_e;
        for (int i = t; i < EPAD * 2 / 16; i += 1024) se[i] = ge[i];
    }
    {
        const int4* gp = (const int4*)(g_perm + nbase);   // 2000B = 125 int4
        int4* sp = (int4*)s_p;
        if (t < 125) sp[t] = gp[t];
    }
    __syncthreads();

    int w = t >> 5, lane = t & 31;
    int sub = lane >> 3;
    int dl = lane & 7;
    float4 bb = *(const float4*)&bias[q * 32 + dl * 4];
    float4 psum = make_float4(0.f, 0.f, 0.f, 0.f);

    for (int n0 = w * 4; n0 < NPG; n0 += 128) {
        int slot = n0 + sub;
        bool valid = (slot < NPG);
        int vp = valid ? (int)s_p[slot] : 0;   // degree-sorted node id
        int cnt = valid ? g_deg[nbase + vp] : 0;
        int start = g_rowptr[nbase + vp];      // local, multiple of 8

        float4 acc = make_float4(0.f, 0.f, 0.f, 0.f);
        if (valid) acc = *(const float4*)&s_x[vp * 32 + dl * 4];  // self-loop

        for (int c = 0; c < cnt; c += 8) {
            uint4 iw = *(const uint4*)&s_e[start + c];   // 8 u16 indices, aligned
            int rem = cnt - c;
            uint32_t parts[4] = {iw.x, iw.y, iw.z, iw.w};
            #pragma unroll
            for (int j = 0; j < 8; j++) {
                int sj = (int)((parts[j >> 1] >> ((j & 1) * 16)) & 0xffffu);
                if (j < rem) {
                    float4 xs = *(const float4*)&s_x[sj * 32 + dl * 4];
                    acc.x += xs.x; acc.y += xs.y; acc.z += xs.z; acc.w += xs.w;
                }
            }
        }

        if (valid) {
            float dv = g_dinv[nbase + vp];
            float4 res = make_float4(fmaxf(dv * acc.x + bb.x, 0.f),
                                     fmaxf(dv * acc.y + bb.y, 0.f),
                                     fmaxf(dv * acc.z + bb.z, 0.f),
                                     fmaxf(dv * acc.w + bb.w, 0.f));
            if (pool) {
                psum.x += res.x; psum.y += res.y; psum.z += res.z; psum.w += res.w;
            } else {
                *(float4*)&OUT[(size_t)(nbase + vp) * DD + q * 32 + dl * 4] = res;
            }
        }
    }

    if (pool) {
        unsigned mm = 0xffffffffu;
        psum.x += __shfl_down_sync(mm, psum.x, 16);
        psum.y += __shfl_down_sync(mm, psum.y, 16);
        psum.z += __shfl_down_sync(mm, psum.z, 16);
        psum.w += __shfl_down_sync(mm, psum.w, 16);
        psum.x += __shfl_down_sync(mm, psum.x, 8);
        psum.y += __shfl_down_sync(mm, psum.y, 8);
        psum.z += __shfl_down_sync(mm, psum.z, 8);
        psum.w += __shfl_down_sync(mm, psum.w, 8);
        if (lane < 8) *(float4*)&s_ws[w * 32 + lane * 4] = psum;
        __syncthreads();
        if (t < 32) {
            float sum = 0.f;
            #pragma unroll 8
            for (int ww = 0; ww < 32; ww++) sum += s_ws[ww * 32 + t];
            pool[b * DD + q * 32 + t] = sum * (1.0f / KK);
        }
    }
}

// ---------------- final MLP ----------------
__global__ void k_mlp(const float* __restrict__ W1, const float* __restrict__ b1,
                      const float* __restrict__ W2, const float* __restrict__ b2,
                      float* __restrict__ out) {
    int b = blockIdx.x;
    int t = threadIdx.x;
    __shared__ float p[128], h[128];
    p[t] = g_pool[b * 128 + t];
    __syncthreads();
    float acc = b1[t];
    #pragma unroll 4
    for (int d = 0; d < 128; d++) acc += p[d] * W1[d * 128 + t];
    h[t] = fmaxf(acc, 0.f);
    __syncthreads();
    if (t < 10) {
        float o = b2[t];
        #pragma unroll 4
        for (int j = 0; j < 128; j++) o += h[j] * W2[j * 10 + t];
        out[b * 10 + t] = o;
    }
}

// ---------------- launch (EXACT R13 fork-join shape; s2 first op waits evFork) -
extern "C" void kernel_launch(void* const* d_in, const int* in_sizes, int n_in,
                              void* d_out, int out_size) {
    const float* x     = (const float*)d_in[0];
    const int*   ei    = (const int*)d_in[1];
    const float* W_pre = (const float*)d_in[3];
    const float* b_pre = (const float*)d_in[4];
    const float* W_emb = (const float*)d_in[5];
    const float* b_emb = (const float*)d_in[6];
    // d_in[2] batch, d_in[7] W_asn, d_in[8] b_asn dead (softmax rows sum to 1)
    const float* W1 = (const float*)d_in[9];
    const float* b1 = (const float*)d_in[10];
    const float* W2 = (const float*)d_in[11];
    const float* b2 = (const float*)d_in[12];
    float* out = (float*)d_out;

    int E = in_sizes[1] / 2;
    int N = in_sizes[0] / DD;
    const int* src = ei;
    const int* dst = ei + E;

    void *pA, *pB, *pP, *pWhp, *pWlp, *pWhe, *pWle;
    cudaGetSymbolAddress(&pA, g_bufA);
    cudaGetSymbolAddress(&pB, g_bufB);
    cudaGetSymbolAddress(&pP, g_pool);
    cudaGetSymbolAddress(&pWhp, g_Wh_pre);
    cudaGetSymbolAddress(&pWlp, g_Wl_pre);
    cudaGetSymbolAddress(&pWhe, g_Wh_emb);
    cudaGetSymbolAddress(&pWle, g_Wl_emb);
    float* bufA = (float*)pA;
    float* bufB = (float*)pB;

    const int smem_mma = 98304;                                       // 96KB, 2 CTAs/SM
    const int smem_agg = NPG * 32 * 4 + EPAD * 2 + 4096 + 2048;       // 182144B
    cudaFuncSetAttribute(k_gemm_mma, cudaFuncAttributeMaxDynamicSharedMemorySize, smem_mma);
    cudaFuncSetAttribute(k_agg, cudaFuncAttributeMaxDynamicSharedMemorySize, smem_agg);

    // side stream + events for fork-join (lazy init; host resources only)
    static cudaStream_t s2 = 0;
    static cudaEvent_t evFork = 0, evJoin = 0;
    if (!s2) {
        cudaStreamCreateWithFlags(&s2, cudaStreamNonBlocking);
        cudaEventCreateWithFlags(&evFork, cudaEventDisableTiming);
        cudaEventCreateWithFlags(&evJoin, cudaEventDisableTiming);
    }

    // serial prerequisites of GEMM1 on the capture stream: weight images + dinv
    k_prepW<<<64, 256>>>(W_pre, W_emb);
    k_deg<<<BBG, 1024>>>(dst);

    // fork: CSR fill + degree sort (needed only by agg1) overlaps GEMM1
    cudaEventRecord(evFork, 0);
    cudaStreamWaitEvent(s2, evFork, 0);       // s2's FIRST op joins the capture
    k_fill<<<BBG, 1024, 0, s2>>>(src, dst);
    cudaEventRecord(evJoin, s2);

    // conv1: h = relu(Ahat @ (x @ W_pre) + b_pre)   [dinv folded into GEMM rows]
    k_gemm_mma<<<N / 64, 256, smem_mma>>>(x, (const char*)pWhp, (const char*)pWlp, bufA);
    cudaStreamWaitEvent(0, evJoin, 0);   // join before aggregation
    k_agg<<<dim3(BBG, 4), 1024, smem_agg>>>(bufA, bufB, b_pre, nullptr);

    // conv2: NE = relu(Ahat @ (h @ W_emb) + b_emb); mean-pool fused into agg
    k_gemm_mma<<<N / 64, 256, smem_mma>>>(bufB, (const char*)pWhe, (const char*)pWle, bufA);
    k_agg<<<dim3(BBG, 4), 1024, smem_agg>>>(bufA, bufB, b_emb, (float*)pP);

    // MLP head
    k_mlp<<<BBG, 128>>>(W1, b1, W2, b2, out);
}

// round 16
// speedup vs baseline: 1.2377x; 1.0142x over previous
#include <cuda_runtime.h>
#include <cuda_bf16.h>
#include <math.h>
#include <stdint.h>

#define NN  128000   // B*NPG nodes
#define EE  2048000  // B*EPG edges
#define BBG 128      // graphs
#define NPG 1000
#define EPG 16000
#define DD  128
#define KK  64
#define EPAD 24000   // padded per-graph CSR capacity

// ---------------- scratch (static device globals; no allocs) ----------------
__device__ int      g_deg[NN];
__device__ float    g_dinv[NN];
__device__ int      g_rowptr[NN];              // graph-LOCAL padded CSR offset (mult of 8)
__device__ unsigned short g_csr16[BBG * EPAD]; // graph-local src index per edge
__device__ unsigned short g_perm[NN];          // degree-sorted node permutation (local)
__device__ float    g_bufA[(size_t)NN * DD];
__device__ float    g_bufB[(size_t)NN * DD];
__device__ float    g_pool[BBG * DD];
// bf16 hi/lo weight images, PRE-SWIZZLED into the exact smem byte layout
__device__ char  g_Wh_pre[32768];
__device__ char  g_Wl_pre[32768];
__device__ char  g_Wh_emb[32768];
__device__ char  g_Wl_emb[32768];

// ---------------- warp-MMA helpers (base ISA; proven R9-R15) ------------------
__device__ __forceinline__ uint32_t smem_u32(const void* p) {
    uint32_t a;
    asm("{ .reg .u64 t; cvta.to.shared.u64 t, %1; cvt.u32.u64 %0, t; }" : "=r"(a) : "l"(p));
    return a;
}
__device__ __forceinline__ void ldsm_x4(uint32_t* r, uint32_t a) {
    asm volatile("ldmatrix.sync.aligned.m8n8.x4.shared.b16 {%0,%1,%2,%3}, [%4];"
                 : "=r"(r[0]), "=r"(r[1]), "=r"(r[2]), "=r"(r[3]) : "r"(a));
}
__device__ __forceinline__ void ldsm_x2t(uint32_t* r, uint32_t a) {
    asm volatile("ldmatrix.sync.aligned.m8n8.x2.trans.shared.b16 {%0,%1}, [%2];"
                 : "=r"(r[0]), "=r"(r[1]) : "r"(a));
}
__device__ __forceinline__ void mma16816(float* d, const uint32_t* a, const uint32_t* b) {
    asm volatile("mma.sync.aligned.m16n8k16.row.col.f32.bf16.bf16.f32 "
                 "{%0,%1,%2,%3}, {%4,%5,%6,%7}, {%8,%9}, {%0,%1,%2,%3};"
                 : "+f"(d[0]), "+f"(d[1]), "+f"(d[2]), "+f"(d[3])
                 : "r"(a[0]), "r"(a[1]), "r"(a[2]), "r"(a[3]), "r"(b[0]), "r"(b[1]));
}
__device__ __forceinline__ uint32_t pack_bf16(__nv_bfloat16 lo, __nv_bfloat16 hi) {
    return ((uint32_t)__bfloat16_as_ushort(hi) << 16) | __bfloat16_as_ushort(lo);
}

// ---------------- degree + dinv (now OFF the critical path) -------------------
__global__ __launch_bounds__(1024) void k_deg(const int* __restrict__ dst) {
    __shared__ int cnt[NPG];
    int b = blockIdx.x, t = threadIdx.x;
    int ebase = b * EPG, nbase = b * NPG;
    if (t < NPG) cnt[t] = 0;
    __syncthreads();
    for (int e = t; e < EPG; e += 1024)
        atomicAdd(&cnt[dst[ebase + e] - nbase], 1);
    __syncthreads();
    if (t < NPG) {
        int val = cnt[t];
        g_deg[nbase + t]  = val;
        g_dinv[nbase + t] = rsqrtf((float)(val + 1));  // +1 self-loop
    }
}

// ---------------- CSR fill + degree-sorted permutation (overlaps GEMM1) -------
__global__ __launch_bounds__(1024) void k_fill(const int* __restrict__ src,
                                               const int* __restrict__ dst) {
    __shared__ int cnt[NPG];
    __shared__ int ws[32];
    __shared__ int bcnt[64];
    __shared__ int bstart[64];
    int b = blockIdx.x, t = threadIdx.x;
    int ebase = b * EPG, nbase = b * NPG;

    int val = (t < NPG) ? g_deg[nbase + t] : 0;
    int pc = (val + 7) & ~7;            // padded to multiple of 8
    int x = pc;
    unsigned m = 0xffffffffu;
    #pragma unroll
    for (int o = 1; o < 32; o <<= 1) {
        int y = __shfl_up_sync(m, x, o);
        if ((t & 31) >= o) x += y;
    }
    if ((t & 31) == 31) ws[t >> 5] = x;
    if (t < 64) bcnt[t] = 0;
    __syncthreads();
    if (t < 32) {
        int y = ws[t];
        int z = y;
        #pragma unroll
        for (int o = 1; o < 32; o <<= 1) {
            int w = __shfl_up_sync(m, z, o);
            if (t >= o) z += w;
        }
        ws[t] = z - y;
    }
    __syncthreads();
    int excl = x + ws[t >> 5] - pc;
    __syncthreads();

    // degree-bucket rank (counting sort, 64 buckets)
    int mybkt = min(val, 63);
    int brank = 0;
    if (t < NPG) {
        g_rowptr[nbase + t] = excl;     // LOCAL padded offset (mult of 8)
        cnt[t] = excl;                  // cursor
        brank = atomicAdd(&bcnt[mybkt], 1);
    }
    __syncthreads();
    if (t == 0) {
        int s = 0;
        #pragma unroll
        for (int i = 0; i < 64; i++) { bstart[i] = s; s += bcnt[i]; }
    }
    __syncthreads();
    if (t < NPG)
        g_perm[nbase + bstart[mybkt] + brank] = (unsigned short)t;

    unsigned short* out16 = g_csr16 + (size_t)b * EPAD;
    for (int e = t; e < EPG; e += 1024) {
        int s = src[ebase + e] - nbase;
        int d = dst[ebase + e] - nbase;
        int p = atomicAdd(&cnt[d], 1);
        out16[p] = (unsigned short)s;
    }
}

// ---------------- weight prep: bf16 hi/lo split into swizzled smem images -----
__global__ void k_prepW(const float* __restrict__ Wp, const float* __restrict__ We) {
    int id = blockIdx.x * 256 + threadIdx.x;
    if (id >= DD * DD) return;
    int k = id >> 7, n = id & 127;
    uint32_t off = (uint32_t)k * 256 + (((uint32_t)n * 2) ^ (((uint32_t)k & 7) << 4));

    float w = Wp[id];
    __nv_bfloat16 h = __float2bfloat16(w);
    *(__nv_bfloat16*)(g_Wh_pre + off) = h;
    *(__nv_bfloat16*)(g_Wl_pre + off) = __float2bfloat16(w - __bfloat162float(h));

    w = We[id];
    h = __float2bfloat16(w);
    *(__nv_bfloat16*)(g_Wh_emb + off) = h;
    *(__nv_bfloat16*)(g_Wl_emb + off) = __float2bfloat16(w - __bfloat162float(h));
}

// ---------------- GEMM via mma.sync bf16 (3-term hi/lo), 2x4 warp layout ------
// O = X @ W (raw; dinv applied downstream in k_agg's slice load).
// 64-row tile, 256 threads (8 warps), grid 2000, 96KB smem -> 2 CTAs/SM.
// Warp (wr = w>>2 in {0,1} row half; wc = w&3 col group of 32):
//   A fragments duplicated 4x (was 8x), B duplicated 2x (was 1x)
//   -> crossbar traffic per kc: 32KB vs 40KB (-20%).
__global__ __launch_bounds__(256) void k_gemm_mma(const float* __restrict__ X,
                                                  const char* __restrict__ WhI,
                                                  const char* __restrict__ WlI,
                                                  float* __restrict__ O) {
    extern __shared__ __align__(1024) char smem[];
    char* sXh = smem;                 // 64*256 = 16KB
    char* sXl = smem + 16384;
    char* sWh = smem + 32768;
    char* sWl = smem + 65536;
    int t = threadIdx.x;
    size_t row0 = (size_t)blockIdx.x * 64;

    {
        const int4* s1 = (const int4*)WhI;
        const int4* s2 = (const int4*)WlI;
        int4* d1 = (int4*)sWh;
        int4* d2 = (int4*)sWl;
        #pragma unroll
        for (int i = 0; i < 8; i++) {
            d1[i * 256 + t] = s1[i * 256 + t];
            d2[i * 256 + t] = s2[i * 256 + t];
        }
    }
    {
        const float4* X4 = (const float4*)(X + row0 * DD);
        #pragma unroll
        for (int i = 0; i < 8; i++) {
            int gid = i * 256 + t;
            int r = gid >> 5, c4 = gid & 31;
            float4 v = X4[gid];
            __nv_bfloat16 h0 = __float2bfloat16(v.x), h1 = __float2bfloat16(v.y);
            __nv_bfloat16 h2 = __float2bfloat16(v.z), h3 = __float2bfloat16(v.w);
            __nv_bfloat16 l0 = __float2bfloat16(v.x - __bfloat162float(h0));
            __nv_bfloat16 l1 = __float2bfloat16(v.y - __bfloat162float(h1));
            __nv_bfloat16 l2 = __float2bfloat16(v.z - __bfloat162float(h2));
            __nv_bfloat16 l3 = __float2bfloat16(v.w - __bfloat162float(h3));
            uint32_t off = (uint32_t)r * 256 + (((uint32_t)c4 * 8) ^ (((uint32_t)r & 7) << 4));
            *(uint2*)(sXh + off) = make_uint2(pack_bf16(h0, h1), pack_bf16(h2, h3));
            *(uint2*)(sXl + off) = make_uint2(pack_bf16(l0, l1), pack_bf16(l2, l3));
        }
    }
    __syncthreads();

    int w = t >> 5, lane = t & 31;
    int wr = w >> 2;      // 0..1: row half (32 rows = rg pair)
    int wc = w & 3;       // 0..3: col group (32 cols = 4 n-tiles)
    int lr15 = lane & 15;
    uint32_t axor = (uint32_t)(lr15 & 7) << 4;
    uint32_t acolb = (uint32_t)(lane >> 4) * 16;

    uint32_t uXh = smem_u32(sXh), uXl = smem_u32(sXl);
    uint32_t uWh = smem_u32(sWh), uWl = smem_u32(sWl);

    float acc[2][4][4];
    #pragma unroll
    for (int rgl = 0; rgl < 2; rgl++)
        #pragma unroll
        for (int nt = 0; nt < 4; nt++)
            #pragma unroll
            for (int j = 0; j < 4; j++) acc[rgl][nt][j] = 0.f;

    #pragma unroll
    for (int kc = 0; kc < 8; kc++) {
        uint32_t bh[4][2], bl[4][2];
        uint32_t brow = (uint32_t)(kc * 16 + lr15) * 256;
        #pragma unroll
        for (int nt = 0; nt < 4; nt++) {
            uint32_t cb = (((uint32_t)wc * 64 + (uint32_t)nt * 16) ^ axor);
            ldsm_x2t(bh[nt], uWh + brow + cb);
            ldsm_x2t(bl[nt], uWl + brow + cb);
        }
        uint32_t acb = (((uint32_t)kc * 32 + acolb) ^ axor);
        uint32_t arow = (uint32_t)lr15 * 256;
        #pragma unroll
        for (int rgl = 0; rgl < 2; rgl++) {
            int rg = wr * 2 + rgl;
            uint32_t ah[4], al[4];
            uint32_t aoff = (uint32_t)rg * 4096 + arow + acb;
            ldsm_x4(ah, uXh + aoff);
            ldsm_x4(al, uXl + aoff);
            #pragma unroll
            for (int nt = 0; nt < 4; nt++) {
                mma16816(acc[rgl][nt], ah, bh[nt]);
                mma16816(acc[rgl][nt], ah, bl[nt]);
                mma16816(acc[rgl][nt], al, bh[nt]);
            }
        }
    }

    int gid = lane >> 2, tig = lane & 3;
    #pragma unroll
    for (int rgl = 0; rgl < 2; rgl++) {
        int rg = wr * 2 + rgl;
        size_t r0 = row0 + rg * 16 + gid;
        size_t r1 = r0 + 8;
        #pragma unroll
        for (int nt = 0; nt < 4; nt++) {
            int col = wc * 32 + nt * 8 + tig * 2;
            *(float2*)(O + r0 * DD + col) =
                make_float2(acc[rgl][nt][0], acc[rgl][nt][1]);
            *(float2*)(O + r1 * DD + col) =
                make_float2(acc[rgl][nt][2], acc[rgl][nt][3]);
        }
    }
}

// ---------------- aggregation (R15 inner; dinv folded into slice load) --------
// grid (BBG, 4). s_x[row] = dinv[row] * XW[row] (scaled at load, free FMULs).
// OUT[v] = relu(dinv[v] * (sum_{s in in(v)} s_x[s] + s_x[v]) + bias).
__global__ __launch_bounds__(1024, 1) void k_agg(const float* __restrict__ XW,
                                                 float* __restrict__ OUT,
                                                 const float* __restrict__ bias,
                                                 float* __restrict__ pool) {
    extern __shared__ __align__(16) char smraw[];
    float* s_x = (float*)smraw;                                     // 128000 B
    unsigned short* s_e = (unsigned short*)(smraw + NPG * 32 * 4);  // 48000 B
    float* s_ws = (float*)(smraw + NPG * 32 * 4 + EPAD * 2);        // 4096 B
    unsigned short* s_p = (unsigned short*)(smraw + NPG * 32 * 4 + EPAD * 2 + 4096); // 2000 B
    int b = blockIdx.x;
    int q = blockIdx.y;
    int t = threadIdx.x;
    int nbase = b * NPG;

    for (int idx = t; idx < NPG * 8; idx += 1024) {
        int row = idx >> 3;
        int c4 = idx & 7;
        float dv = g_dinv[nbase + row];
        float4 v = *(const float4*)&XW[(size_t)(nbase + row) * DD + q * 32 + c4 * 4];
        v.x *= dv; v.y *= dv; v.z *= dv; v.w *= dv;
        *(float4*)&s_x[row * 32 + c4 * 4] = v;
    }
    {
        const int4* ge = (const int4*)(g_csr16 + (size_t)b * EPAD);
        int4* se = (int4*)s_e;
        for (int i = t; i < EPAD * 2 / 16; i += 1024) se[i] = ge[i];
    }
    {
        const int4* gp = (const int4*)(g_perm + nbase);   // 2000B = 125 int4
        int4* sp = (int4*)s_p;
        if (t < 125) sp[t] = gp[t];
    }
    __syncthreads();

    int w = t >> 5, lane = t & 31;
    int sub = lane >> 3;
    int dl = lane & 7;
    float4 bb = *(const float4*)&bias[q * 32 + dl * 4];
    float4 psum = make_float4(0.f, 0.f, 0.f, 0.f);

    for (int n0 = w * 4; n0 < NPG; n0 += 128) {
        int slot = n0 + sub;
        bool valid = (slot < NPG);
        int vp = valid ? (int)s_p[slot] : 0;   // degree-sorted node id
        int cnt = valid ? g_deg[nbase + vp] : 0;
        int start = g_rowptr[nbase + vp];      // local, multiple of 8

        float4 acc = make_float4(0.f, 0.f, 0.f, 0.f);
        if (valid) acc = *(const float4*)&s_x[vp * 32 + dl * 4];  // self-loop

        for (int c = 0; c < cnt; c += 8) {
            uint4 iw = *(const uint4*)&s_e[start + c];   // 8 u16 indices, aligned
            int rem = cnt - c;
            uint32_t parts[4] = {iw.x, iw.y, iw.z, iw.w};
            #pragma unroll
            for (int j = 0; j < 8; j++) {
                int sj = (int)((parts[j >> 1] >> ((j & 1) * 16)) & 0xffffu);
                if (j < rem) {
                    float4 xs = *(const float4*)&s_x[sj * 32 + dl * 4];
                    acc.x += xs.x; acc.y += xs.y; acc.z += xs.z; acc.w += xs.w;
                }
            }
        }

        if (valid) {
            float dv = g_dinv[nbase + vp];
            float4 res = make_float4(fmaxf(dv * acc.x + bb.x, 0.f),
                                     fmaxf(dv * acc.y + bb.y, 0.f),
                                     fmaxf(dv * acc.z + bb.z, 0.f),
                                     fmaxf(dv * acc.w + bb.w, 0.f));
            if (pool) {
                psum.x += res.x; psum.y += res.y; psum.z += res.z; psum.w += res.w;
            } else {
                *(float4*)&OUT[(size_t)(nbase + vp) * DD + q * 32 + dl * 4] = res;
            }
        }
    }

    if (pool) {
        unsigned mm = 0xffffffffu;
        psum.x += __shfl_down_sync(mm, psum.x, 16);
        psum.y += __shfl_down_sync(mm, psum.y, 16);
        psum.z += __shfl_down_sync(mm, psum.z, 16);
        psum.w += __shfl_down_sync(mm, psum.w, 16);
        psum.x += __shfl_down_sync(mm, psum.x, 8);
        psum.y += __shfl_down_sync(mm, psum.y, 8);
        psum.z += __shfl_down_sync(mm, psum.z, 8);
        psum.w += __shfl_down_sync(mm, psum.w, 8);
        if (lane < 8) *(float4*)&s_ws[w * 32 + lane * 4] = psum;
        __syncthreads();
        if (t < 32) {
            float sum = 0.f;
            #pragma unroll 8
            for (int ww = 0; ww < 32; ww++) sum += s_ws[ww * 32 + t];
            pool[b * DD + q * 32 + t] = sum * (1.0f / KK);
        }
    }
}

// ---------------- final MLP ----------------
__global__ void k_mlp(const float* __restrict__ W1, const float* __restrict__ b1,
                      const float* __restrict__ W2, const float* __restrict__ b2,
                      float* __restrict__ out) {
    int b = blockIdx.x;
    int t = threadIdx.x;
    __shared__ float p[128], h[128];
    p[t] = g_pool[b * 128 + t];
    __syncthreads();
    float acc = b1[t];
    #pragma unroll 4
    for (int d = 0; d < 128; d++) acc += p[d] * W1[d * 128 + t];
    h[t] = fmaxf(acc, 0.f);
    __syncthreads();
    if (t < 10) {
        float o = b2[t];
        #pragma unroll 4
        for (int j = 0; j < 128; j++) o += h[j] * W2[j * 10 + t];
        out[b * 10 + t] = o;
    }
}

// ---------------- launch (R13-proven fork-join; deg+fill both on s2) ----------
extern "C" void kernel_launch(void* const* d_in, const int* in_sizes, int n_in,
                              void* d_out, int out_size) {
    const float* x     = (const float*)d_in[0];
    const int*   ei    = (const int*)d_in[1];
    const float* W_pre = (const float*)d_in[3];
    const float* b_pre = (const float*)d_in[4];
    const float* W_emb = (const float*)d_in[5];
    const float* b_emb = (const float*)d_in[6];
    // d_in[2] batch, d_in[7] W_asn, d_in[8] b_asn dead (softmax rows sum to 1)
    const float* W1 = (const float*)d_in[9];
    const float* b1 = (const float*)d_in[10];
    const float* W2 = (const float*)d_in[11];
    const float* b2 = (const float*)d_in[12];
    float* out = (float*)d_out;

    int E = in_sizes[1] / 2;
    int N = in_sizes[0] / DD;
    const int* src = ei;
    const int* dst = ei + E;

    void *pA, *pB, *pP, *pWhp, *pWlp, *pWhe, *pWle;
    cudaGetSymbolAddress(&pA, g_bufA);
    cudaGetSymbolAddress(&pB, g_bufB);
    cudaGetSymbolAddress(&pP, g_pool);
    cudaGetSymbolAddress(&pWhp, g_Wh_pre);
    cudaGetSymbolAddress(&pWlp, g_Wl_pre);
    cudaGetSymbolAddress(&pWhe, g_Wh_emb);
    cudaGetSymbolAddress(&pWle, g_Wl_emb);
    float* bufA = (float*)pA;
    float* bufB = (float*)pB;

    const int smem_mma = 98304;                                       // 96KB, 2 CTAs/SM
    const int smem_agg = NPG * 32 * 4 + EPAD * 2 + 4096 + 2048;       // 182144B
    cudaFuncSetAttribute(k_gemm_mma, cudaFuncAttributeMaxDynamicSharedMemorySize, smem_mma);
    cudaFuncSetAttribute(k_agg, cudaFuncAttributeMaxDynamicSharedMemorySize, smem_agg);

    // side stream + events for fork-join (lazy init; host resources only)
    static cudaStream_t s2 = 0;
    static cudaEvent_t evFork = 0, evJoin = 0;
    if (!s2) {
        cudaStreamCreateWithFlags(&s2, cudaStreamNonBlocking);
        cudaEventCreateWithFlags(&evFork, cudaEventDisableTiming);
        cudaEventCreateWithFlags(&evJoin, cudaEventDisableTiming);
    }

    // capture stream: only GEMM1's true prerequisite (weight images) stays serial
    k_prepW<<<64, 256>>>(W_pre, W_emb);

    // fork: deg + CSR fill + degree sort (needed only by agg1) overlap GEMM1
    cudaEventRecord(evFork, 0);
    cudaStreamWaitEvent(s2, evFork, 0);       // s2's FIRST op joins the capture
    k_deg<<<BBG, 1024, 0, s2>>>(dst);
    k_fill<<<BBG, 1024, 0, s2>>>(src, dst);
    cudaEventRecord(evJoin, s2);

    // conv1: h = relu(Ahat @ (x @ W_pre) + b_pre)
    k_gemm_mma<<<N / 64, 256, smem_mma>>>(x, (const char*)pWhp, (const char*)pWlp, bufA);
    cudaStreamWaitEvent(0, evJoin, 0);   // join before aggregation
    k_agg<<<dim3(BBG, 4), 1024, smem_agg>>>(bufA, bufB, b_pre, nullptr);

    // conv2: NE = relu(Ahat @ (h @ W_emb) + b_emb); mean-pool fused into agg
    k_gemm_mma<<<N / 64, 256, smem_mma>>>(bufB, (const char*)pWhe, (const char*)pWle, bufA);
    k_agg<<<dim3(BBG, 4), 1024, smem_agg>>>(bufA, bufB, b_emb, (float*)pP);

    // MLP head
    k_mlp<<<BBG, 128>>>(W1, b1, W2, b2, out);
}

// round 17
// speedup vs baseline: 1.2859x; 1.0389x over previous
#include <cuda_runtime.h>
#include <cuda_bf16.h>
#include <math.h>
#include <stdint.h>

#define NN  128000   // B*NPG nodes
#define EE  2048000  // B*EPG edges
#define BBG 128      // graphs
#define NPG 1000
#define EPG 16000
#define DD  128
#define KK  64
#define EPAD 24000   // padded per-graph CSR capacity
#define ZROW NPG     // sentinel node index -> zero feature row

// ---------------- scratch (static device globals; no allocs) ----------------
__device__ int      g_deg[NN];
__device__ float    g_dinv[NN];
__device__ int      g_rowptr[NN];              // graph-LOCAL padded CSR offset (mult of 8)
__device__ unsigned short g_csr16[BBG * EPAD]; // graph-local src index (ZROW = pad)
__device__ unsigned short g_perm[NN];          // degree-sorted node permutation (local)
__device__ float    g_bufA[(size_t)NN * DD];
__device__ float    g_bufB[(size_t)NN * DD];
__device__ float    g_pool[BBG * DD];
// bf16 hi/lo weight images, PRE-SWIZZLED into the exact SMEM tile byte layout
__device__ char  g_Wh_pre[32768];
__device__ char  g_Wl_pre[32768];
__device__ char  g_Wh_emb[32768];
__device__ char  g_Wl_emb[32768];

// ---------------- warp-MMA helpers (base ISA; proven R9-R16) ------------------
__device__ __forceinline__ uint32_t smem_u32(const void* p) {
    uint32_t a;
    asm("{ .reg .u64 t; cvta.to.shared.u64 t, %1; cvt.u32.u64 %0, t; }" : "=r"(a) : "l"(p));
    return a;
}
__device__ __forceinline__ void ldsm_x4(uint32_t* r, uint32_t a) {
    asm volatile("ldmatrix.sync.aligned.m8n8.x4.shared.b16 {%0,%1,%2,%3}, [%4];"
                 : "=r"(r[0]), "=r"(r[1]), "=r"(r[2]), "=r"(r[3]) : "r"(a));
}
__device__ __forceinline__ void ldsm_x2t(uint32_t* r, uint32_t a) {
    asm volatile("ldmatrix.sync.aligned.m8n8.x2.trans.shared.b16 {%0,%1}, [%2];"
                 : "=r"(r[0]), "=r"(r[1]) : "r"(a));
}
__device__ __forceinline__ void mma16816(float* d, const uint32_t* a, const uint32_t* b) {
    asm volatile("mma.sync.aligned.m16n8k16.row.col.f32.bf16.bf16.f32 "
                 "{%0,%1,%2,%3}, {%4,%5,%6,%7}, {%8,%9}, {%0,%1,%2,%3};"
                 : "+f"(d[0]), "+f"(d[1]), "+f"(d[2]), "+f"(d[3])
                 : "r"(a[0]), "r"(a[1]), "r"(a[2]), "r"(a[3]), "r"(b[0]), "r"(b[1]));
}
__device__ __forceinline__ uint32_t pack_bf16(__nv_bfloat16 lo, __nv_bfloat16 hi) {
    return ((uint32_t)__bfloat16_as_ushort(hi) << 16) | __bfloat16_as_ushort(lo);
}

// ---------------- fused build: deg + dinv + padded CSR + sort (one kernel) ----
__global__ __launch_bounds__(1024) void k_build(const int* __restrict__ src,
                                                const int* __restrict__ dst) {
    __shared__ int cnt[NPG];
    __shared__ int ws[32];
    __shared__ int bcnt[64];
    __shared__ int bstart[64];
    int b = blockIdx.x, t = threadIdx.x;
    int ebase = b * EPG, nbase = b * NPG;

    if (t < NPG) cnt[t] = 0;
    __syncthreads();
    for (int e = t; e < EPG; e += 1024)
        atomicAdd(&cnt[dst[ebase + e] - nbase], 1);
    __syncthreads();

    int val = (t < NPG) ? cnt[t] : 0;
    int pc = (val + 7) & ~7;            // padded to multiple of 8
    int x = pc;
    unsigned m = 0xffffffffu;
    #pragma unroll
    for (int o = 1; o < 32; o <<= 1) {
        int y = __shfl_up_sync(m, x, o);
        if ((t & 31) >= o) x += y;
    }
    if ((t & 31) == 31) ws[t >> 5] = x;
    if (t < 64) bcnt[t] = 0;
    __syncthreads();
    if (t < 32) {
        int y = ws[t];
        int z = y;
        #pragma unroll
        for (int o = 1; o < 32; o <<= 1) {
            int w = __shfl_up_sync(m, z, o);
            if (t >= o) z += w;
        }
        ws[t] = z - y;
    }
    __syncthreads();
    int excl = x + ws[t >> 5] - pc;
    __syncthreads();

    // degree-bucket rank (counting sort, 64 buckets)
    int mybkt = min(val, 63);
    int brank = 0;
    if (t < NPG) {
        g_deg[nbase + t]    = val;
        g_dinv[nbase + t]   = rsqrtf((float)(val + 1));  // +1 self-loop
        g_rowptr[nbase + t] = excl;     // LOCAL padded offset (mult of 8)
        cnt[t] = excl;                  // cursor
        brank = atomicAdd(&bcnt[mybkt], 1);
    }
    __syncthreads();
    if (t == 0) {
        int s = 0;
        #pragma unroll
        for (int i = 0; i < 64; i++) { bstart[i] = s; s += bcnt[i]; }
    }
    __syncthreads();
    if (t < NPG)
        g_perm[nbase + bstart[mybkt] + brank] = (unsigned short)t;

    unsigned short* out16 = g_csr16 + (size_t)b * EPAD;
    for (int e = t; e < EPG; e += 1024) {
        int s = src[ebase + e] - nbase;
        int d = dst[ebase + e] - nbase;
        int p = atomicAdd(&cnt[d], 1);
        out16[p] = (unsigned short)s;
    }
    __syncthreads();

    // pad each node's tail slots with the zero-row sentinel
    if (t < NPG) {
        for (int p = val; p < pc; p++)
            out16[excl + p] = (unsigned short)ZROW;
    }
}

// ---------------- weight prep: bf16 hi/lo split into swizzled smem images -----
__global__ void k_prepW(const float* __restrict__ Wp, const float* __restrict__ We) {
    int id = blockIdx.x * 256 + threadIdx.x;
    if (id >= DD * DD) return;
    int k = id >> 7, n = id & 127;
    uint32_t off = (uint32_t)k * 256 + (((uint32_t)n * 2) ^ (((uint32_t)k & 7) << 4));

    float w = Wp[id];
    __nv_bfloat16 h = __float2bfloat16(w);
    *(__nv_bfloat16*)(g_Wh_pre + off) = h;
    *(__nv_bfloat16*)(g_Wl_pre + off) = __float2bfloat16(w - __bfloat162float(h));

    w = We[id];
    h = __float2bfloat16(w);
    *(__nv_bfloat16*)(g_Wh_emb + off) = h;
    *(__nv_bfloat16*)(g_Wl_emb + off) = __float2bfloat16(w - __bfloat162float(h));
}

// ---------------- GEMM via mma.sync bf16 (3-term hi/lo), 2x4 warp layout ------
// (exact R16 config: 44.5us proven; dinv applied downstream in k_agg)
__global__ __launch_bounds__(256) void k_gemm_mma(const float* __restrict__ X,
                                                  const char* __restrict__ WhI,
                                                  const char* __restrict__ WlI,
                                                  float* __restrict__ O) {
    extern __shared__ __align__(1024) char smem[];
    char* sXh = smem;                 // 64*256 = 16KB
    char* sXl = smem + 16384;
    char* sWh = smem + 32768;
    char* sWl = smem + 65536;
    int t = threadIdx.x;
    size_t row0 = (size_t)blockIdx.x * 64;

    {
        const int4* s1 = (const int4*)WhI;
        const int4* s2 = (const int4*)WlI;
        int4* d1 = (int4*)sWh;
        int4* d2 = (int4*)sWl;
        #pragma unroll
        for (int i = 0; i < 8; i++) {
            d1[i * 256 + t] = s1[i * 256 + t];
            d2[i * 256 + t] = s2[i * 256 + t];
        }
    }
    {
        const float4* X4 = (const float4*)(X + row0 * DD);
        #pragma unroll
        for (int i = 0; i < 8; i++) {
            int gid = i * 256 + t;
            int r = gid >> 5, c4 = gid & 31;
            float4 v = X4[gid];
            __nv_bfloat16 h0 = __float2bfloat16(v.x), h1 = __float2bfloat16(v.y);
            __nv_bfloat16 h2 = __float2bfloat16(v.z), h3 = __float2bfloat16(v.w);
            __nv_bfloat16 l0 = __float2bfloat16(v.x - __bfloat162float(h0));
            __nv_bfloat16 l1 = __float2bfloat16(v.y - __bfloat162float(h1));
            __nv_bfloat16 l2 = __float2bfloat16(v.z - __bfloat162float(h2));
            __nv_bfloat16 l3 = __float2bfloat16(v.w - __bfloat162float(h3));
            uint32_t off = (uint32_t)r * 256 + (((uint32_t)c4 * 8) ^ (((uint32_t)r & 7) << 4));
            *(uint2*)(sXh + off) = make_uint2(pack_bf16(h0, h1), pack_bf16(h2, h3));
            *(uint2*)(sXl + off) = make_uint2(pack_bf16(l0, l1), pack_bf16(l2, l3));
        }
    }
    __syncthreads();

    int w = t >> 5, lane = t & 31;
    int wr = w >> 2;      // 0..1: row half
    int wc = w & 3;       // 0..3: 32-col group
    int lr15 = lane & 15;
    uint32_t axor = (uint32_t)(lr15 & 7) << 4;
    uint32_t acolb = (uint32_t)(lane >> 4) * 16;

    uint32_t uXh = smem_u32(sXh), uXl = smem_u32(sXl);
    uint32_t uWh = smem_u32(sWh), uWl = smem_u32(sWl);

    float acc[2][4][4];
    #pragma unroll
    for (int rgl = 0; rgl < 2; rgl++)
        #pragma unroll
        for (int nt = 0; nt < 4; nt++)
            #pragma unroll
            for (int j = 0; j < 4; j++) acc[rgl][nt][j] = 0.f;

    #pragma unroll
    for (int kc = 0; kc < 8; kc++) {
        uint32_t bh[4][2], bl[4][2];
        uint32_t brow = (uint32_t)(kc * 16 + lr15) * 256;
        #pragma unroll
        for (int nt = 0; nt < 4; nt++) {
            uint32_t cb = (((uint32_t)wc * 64 + (uint32_t)nt * 16) ^ axor);
            ldsm_x2t(bh[nt], uWh + brow + cb);
            ldsm_x2t(bl[nt], uWl + brow + cb);
        }
        uint32_t acb = (((uint32_t)kc * 32 + acolb) ^ axor);
        uint32_t arow = (uint32_t)lr15 * 256;
        #pragma unroll
        for (int rgl = 0; rgl < 2; rgl++) {
            int rg = wr * 2 + rgl;
            uint32_t ah[4], al[4];
            uint32_t aoff = (uint32_t)rg * 4096 + arow + acb;
            ldsm_x4(ah, uXh + aoff);
            ldsm_x4(al, uXl + aoff);
            #pragma unroll
            for (int nt = 0; nt < 4; nt++) {
                mma16816(acc[rgl][nt], ah, bh[nt]);
                mma16816(acc[rgl][nt], ah, bl[nt]);
                mma16816(acc[rgl][nt], al, bh[nt]);
            }
        }
    }

    int gid = lane >> 2, tig = lane & 3;
    #pragma unroll
    for (int rgl = 0; rgl < 2; rgl++) {
        int rg = wr * 2 + rgl;
        size_t r0 = row0 + rg * 16 + gid;
        size_t r1 = r0 + 8;
        #pragma unroll
        for (int nt = 0; nt < 4; nt++) {
            int col = wc * 32 + nt * 8 + tig * 2;
            *(float2*)(O + r0 * DD + col) =
                make_float2(acc[rgl][nt][0], acc[rgl][nt][1]);
            *(float2*)(O + r1 * DD + col) =
                make_float2(acc[rgl][nt][2], acc[rgl][nt][3]);
        }
    }
}

// ---------------- aggregation (branch-free inner via zero-row sentinel) -------
// grid (BBG, 4). s_x[row] = dinv[row]*XW[row] for row<NPG; s_x[ZROW] = 0.
// CSR segments are 8-padded with ZROW -> inner loop has NO predication.
// OUT[v] = relu(dinv[v] * (sum s_x[s] + s_x[v]) + bias); pool mode fuses mean/K.
__global__ __launch_bounds__(1024, 1) void k_agg(const float* __restrict__ XW,
                                                 float* __restrict__ OUT,
                                                 const float* __restrict__ bias,
                                                 float* __restrict__ pool) {
    extern __shared__ __align__(16) char smraw[];
    float* s_x = (float*)smraw;                                      // 1001*32*4 = 128128 B
    unsigned short* s_e = (unsigned short*)(smraw + 128128);         // 48000 B
    float* s_ws = (float*)(smraw + 128128 + 48000);                  // 4096 B
    unsigned short* s_p = (unsigned short*)(smraw + 128128 + 48000 + 4096); // 2000 B
    int b = blockIdx.x;
    int q = blockIdx.y;
    int t = threadIdx.x;
    int nbase = b * NPG;

    for (int idx = t; idx < NPG * 8; idx += 1024) {
        int row = idx >> 3;
        int c4 = idx & 7;
        float dv = g_dinv[nbase + row];
        float4 v = *(const float4*)&XW[(size_t)(nbase + row) * DD + q * 32 + c4 * 4];
        v.x *= dv; v.y *= dv; v.z *= dv; v.w *= dv;
        *(float4*)&s_x[row * 32 + c4 * 4] = v;
    }
    if (t < 8)   // zero sentinel row
        *(float4*)&s_x[ZROW * 32 + t * 4] = make_float4(0.f, 0.f, 0.f, 0.f);
    {
        const int4* ge = (const int4*)(g_csr16 + (size_t)b * EPAD);
        int4* se = (int4*)s_e;
        for (int i = t; i < EPAD * 2 / 16; i += 1024) se[i] = ge[i];
    }
    {
        const int4* gp = (const int4*)(g_perm + nbase);   // 2000B = 125 int4
        int4* sp = (int4*)s_p;
        if (t < 125) sp[t] = gp[t];
    }
    __syncthreads();

    int w = t >> 5, lane = t & 31;
    int sub = lane >> 3;
    int dl = lane & 7;
    float4 bb = *(const float4*)&bias[q * 32 + dl * 4];
    float4 psum = make_float4(0.f, 0.f, 0.f, 0.f);

    for (int n0 = w * 4; n0 < NPG; n0 += 128) {
        int slot = n0 + sub;
        bool valid = (slot < NPG);
        int vp = valid ? (int)s_p[slot] : 0;   // degree-sorted node id
        int deg = valid ? g_deg[nbase + vp] : 0;
        int pc = (deg + 7) & ~7;               // padded count (sentinel-filled)
        int start = g_rowptr[nbase + vp];      // local, multiple of 8

        float4 acc = make_float4(0.f, 0.f, 0.f, 0.f);
        if (valid) acc = *(const float4*)&s_x[vp * 32 + dl * 4];  // self-loop

        for (int c = 0; c < pc; c += 8) {
            uint4 iw = *(const uint4*)&s_e[start + c];   // 8 u16 indices, aligned
            uint32_t parts[4] = {iw.x, iw.y, iw.z, iw.w};
            #pragma unroll
            for (int j = 0; j < 8; j++) {
                int sj = (int)((parts[j >> 1] >> ((j & 1) * 16)) & 0xffffu);
                float4 xs = *(const float4*)&s_x[sj * 32 + dl * 4];
                acc.x += xs.x; acc.y += xs.y; acc.z += xs.z; acc.w += xs.w;
            }
        }

        if (valid) {
            float dv = g_dinv[nbase + vp];
            float4 res = make_float4(fmaxf(dv * acc.x + bb.x, 0.f),
                                     fmaxf(dv * acc.y + bb.y, 0.f),
                                     fmaxf(dv * acc.z + bb.z, 0.f),
                                     fmaxf(dv * acc.w + bb.w, 0.f));
            if (pool) {
                psum.x += res.x; psum.y += res.y; psum.z += res.z; psum.w += res.w;
            } else {
                *(float4*)&OUT[(size_t)(nbase + vp) * DD + q * 32 + dl * 4] = res;
            }
        }
    }

    if (pool) {
        unsigned mm = 0xffffffffu;
        psum.x += __shfl_down_sync(mm, psum.x, 16);
        psum.y += __shfl_down_sync(mm, psum.y, 16);
        psum.z += __shfl_down_sync(mm, psum.z, 16);
        psum.w += __shfl_down_sync(mm, psum.w, 16);
        psum.x += __shfl_down_sync(mm, psum.x, 8);
        psum.y += __shfl_down_sync(mm, psum.y, 8);
        psum.z += __shfl_down_sync(mm, psum.z, 8);
        psum.w += __shfl_down_sync(mm, psum.w, 8);
        if (lane < 8) *(float4*)&s_ws[w * 32 + lane * 4] = psum;
        __syncthreads();
        if (t < 32) {
            float sum = 0.f;
            #pragma unroll 8
            for (int ww = 0; ww < 32; ww++) sum += s_ws[ww * 32 + t];
            pool[b * DD + q * 32 + t] = sum * (1.0f / KK);
        }
    }
}

// ---------------- final MLP ----------------
__global__ void k_mlp(const float* __restrict__ W1, const float* __restrict__ b1,
                      const float* __restrict__ W2, const float* __restrict__ b2,
                      float* __restrict__ out) {
    int b = blockIdx.x;
    int t = threadIdx.x;
    __shared__ float p[128], h[128];
    p[t] = g_pool[b * 128 + t];
    __syncthreads();
    float acc = b1[t];
    #pragma unroll 4
    for (int d = 0; d < 128; d++) acc += p[d] * W1[d * 128 + t];
    h[t] = fmaxf(acc, 0.f);
    __syncthreads();
    if (t < 10) {
        float o = b2[t];
        #pragma unroll 4
        for (int j = 0; j < 128; j++) o += h[j] * W2[j * 10 + t];
        out[b * 10 + t] = o;
    }
}

// ---------------- launch (R13-proven fork-join; build on s2 under GEMM1) ------
extern "C" void kernel_launch(void* const* d_in, const int* in_sizes, int n_in,
                              void* d_out, int out_size) {
    const float* x     = (const float*)d_in[0];
    const int*   ei    = (const int*)d_in[1];
    const float* W_pre = (const float*)d_in[3];
    const float* b_pre = (const float*)d_in[4];
    const float* W_emb = (const float*)d_in[5];
    const float* b_emb = (const float*)d_in[6];
    // d_in[2] batch, d_in[7] W_asn, d_in[8] b_asn dead (softmax rows sum to 1)
    const float* W1 = (const float*)d_in[9];
    const float* b1 = (const float*)d_in[10];
    const float* W2 = (const float*)d_in[11];
    const float* b2 = (const float*)d_in[12];
    float* out = (float*)d_out;

    int E = in_sizes[1] / 2;
    int N = in_sizes[0] / DD;
    const int* src = ei;
    const int* dst = ei + E;

    void *pA, *pB, *pP, *pWhp, *pWlp, *pWhe, *pWle;
    cudaGetSymbolAddress(&pA, g_bufA);
    cudaGetSymbolAddress(&pB, g_bufB);
    cudaGetSymbolAddress(&pP, g_pool);
    cudaGetSymbolAddress(&pWhp, g_Wh_pre);
    cudaGetSymbolAddress(&pWlp, g_Wl_pre);
    cudaGetSymbolAddress(&pWhe, g_Wh_emb);
    cudaGetSymbolAddress(&pWle, g_Wl_emb);
    float* bufA = (float*)pA;
    float* bufB = (float*)pB;

    const int smem_mma = 98304;                                  // 96KB, 2 CTAs/SM
    const int smem_agg = 128128 + 48000 + 4096 + 2048;           // 182272B
    cudaFuncSetAttribute(k_gemm_mma, cudaFuncAttributeMaxDynamicSharedMemorySize, smem_mma);
    cudaFuncSetAttribute(k_agg, cudaFuncAttributeMaxDynamicSharedMemorySize, smem_agg);

    // side stream + events for fork-join (lazy init; host resources only)
    static cudaStream_t s2 = 0;
    static cudaEvent_t evFork = 0, evJoin = 0;
    if (!s2) {
        cudaStreamCreateWithFlags(&s2, cudaStreamNonBlocking);
        cudaEventCreateWithFlags(&evFork, cudaEventDisableTiming);
        cudaEventCreateWithFlags(&evJoin, cudaEventDisableTiming);
    }

    // capture stream: GEMM1's true prerequisite (weight images)
    k_prepW<<<64, 256>>>(W_pre, W_emb);

    // fork: fused build (deg+dinv+CSR+sort+pad; needed only by agg1) overlaps GEMM1
    cudaEventRecord(evFork, 0);
    cudaStreamWaitEvent(s2, evFork, 0);       // s2's FIRST op joins the capture
    k_build<<<BBG, 1024, 0, s2>>>(src, dst);
    cudaEventRecord(evJoin, s2);

    // conv1: h = relu(Ahat @ (x @ W_pre) + b_pre)
    k_gemm_mma<<<N / 64, 256, smem_mma>>>(x, (const char*)pWhp, (const char*)pWlp, bufA);
    cudaStreamWaitEvent(0, evJoin, 0);   // join before aggregation
    k_agg<<<dim3(BBG, 4), 1024, smem_agg>>>(bufA, bufB, b_pre, nullptr);

    // conv2: NE = relu(Ahat @ (h @ W_emb) + b_emb); mean-pool fused into agg
    k_gemm_mma<<<N / 64, 256, smem_mma>>>(bufB, (const char*)pWhe, (const char*)pWle, bufA);
    k_agg<<<dim3(BBG, 4), 1024, smem_agg>>>(bufA, bufB, b_emb, (float*)pP);

    // MLP head
    k_mlp<<<BBG, 128>>>(W1, b1, W2, b2, out);
}